// round 14
// baseline (speedup 1.0000x reference)
#include <cuda_runtime.h>
#include <cuda_fp16.h>
#include <math.h>
#include <stdint.h>

// Problem dims (fixed for this instance)
#define BB   4
#define LL   2048
#define DM   768
#define DIN  1536
#define NN   16
#define KK   4
#define BL   (BB*LL)          // 8192 tokens
#define CH   16               // scan chunks
#define CLEN (LL/CH)          // 128

#define NWIN  (2*DIN*DM)      // 2359296
#define NWOUT (DM*DIN)        // 1179648

// ----------------------------------------------------------------------------
// Device scratch
// ----------------------------------------------------------------------------
__device__ __half g_xz [BL*2*DIN];               // bitlinear output [x_path | z] (fp16)
__device__ __half g_xc [BL*DIN];                 // conv + silu (fp16)
__device__ float  g_dbc[BL*33];                  // [dt | B(16) | C(16)]
__device__ __half g_y  [BL*DIN];                 // scan output * silu(z) (fp16)
__device__ __half g_A1[BL*DM];                   // fp16 rmsnorm2(x) [M, DM]
__device__ __half g_A2[BL*DIN];                  // fp16 rmsnorm(y)  [M, DIN]
__device__ __half g_B1[NWIN];                    // ternary W_in  fp16 [3072, 768]
__device__ __half g_B2[NWOUT];                   // ternary W_out fp16 [768, 1536]
__device__ float g_carry[BB*CH*DIN*NN];          // chunk carries / h_in (in-place)
__device__ float g_sumd [BB*CH*DIN];             // per-chunk sum of delta
__device__ float g_part[512];                    // reduction partials
__device__ float g_scale[2];                     // scales for W_in / W_out

// ----------------------------------------------------------------------------
// Helpers
// ----------------------------------------------------------------------------
__device__ __forceinline__ float block_reduce_sum(float v, float* sred) {
    #pragma unroll
    for (int s = 16; s; s >>= 1) v += __shfl_xor_sync(0xffffffffu, v, s);
    int w = threadIdx.x >> 5;
    __syncthreads();
    if ((threadIdx.x & 31) == 0) sred[w] = v;
    __syncthreads();
    float t = 0.f;
    int nw = blockDim.x >> 5;
    for (int i = 0; i < nw; i++) t += sred[i];
    return t;
}

__device__ __forceinline__ float silu_f(float x) {
    return x / (1.f + __expf(-x));
}

// silu via tanh.approx (1 MUFU instead of 2)
__device__ __forceinline__ float silu_tanh(float x) {
    float t;
    asm("tanh.approx.f32 %0, %1;" : "=f"(t) : "f"(x * 0.5f));
    return 0.5f * x * (1.f + t);
}

__device__ __forceinline__ float softplus_f(float x) {
    return (x > 20.f) ? x : __logf(1.f + __expf(x));
}

__device__ __forceinline__ uint32_t cvta_s(const void* p) {
    return (uint32_t)__cvta_generic_to_shared(p);
}

__device__ __forceinline__ void cpa16(uint32_t s, const void* g) {
    asm volatile("cp.async.cg.shared.global [%0], [%1], 16;" :: "r"(s), "l"(g));
}
__device__ __forceinline__ void cpa_commit() {
    asm volatile("cp.async.commit_group;");
}
template <int N_>
__device__ __forceinline__ void cpa_wait() {
    asm volatile("cp.async.wait_group %0;" :: "n"(N_));
}

__device__ __forceinline__ void ldsm4(uint32_t& r0, uint32_t& r1, uint32_t& r2, uint32_t& r3,
                                      uint32_t addr) {
    asm volatile("ldmatrix.sync.aligned.m8n8.x4.shared.b16 {%0,%1,%2,%3}, [%4];"
                 : "=r"(r0), "=r"(r1), "=r"(r2), "=r"(r3) : "r"(addr));
}

__device__ __forceinline__ void mma16816(float* d, const uint32_t* a, const uint32_t* b) {
    asm volatile("mma.sync.aligned.m16n8k16.row.col.f32.f16.f16.f32 "
                 "{%0,%1,%2,%3},{%4,%5,%6,%7},{%8,%9},{%0,%1,%2,%3};"
                 : "+f"(d[0]), "+f"(d[1]), "+f"(d[2]), "+f"(d[3])
                 : "r"(a[0]), "r"(a[1]), "r"(a[2]), "r"(a[3]), "r"(b[0]), "r"(b[1]));
}

// dA[j] = E^(j+1), j=0..15, log-depth multiply tree
__device__ __forceinline__ void epowers16(float E, float* dA) {
    dA[0] = E;
    dA[1] = E * E;
    dA[2] = dA[1] * E;
    dA[3] = dA[1] * dA[1];
    dA[4] = dA[3] * E;
    dA[5] = dA[3] * dA[1];
    dA[6] = dA[3] * dA[2];
    dA[7] = dA[3] * dA[3];
    dA[8] = dA[7] * E;
    dA[9] = dA[7] * dA[1];
    dA[10] = dA[7] * dA[2];
    dA[11] = dA[7] * dA[3];
    dA[12] = dA[7] * dA[4];
    dA[13] = dA[7] * dA[5];
    dA[14] = dA[7] * dA[6];
    dA[15] = dA[7] * dA[7];
}

// ----------------------------------------------------------------------------
// Weight quantization (deterministic 2-phase mean|W|)
// ----------------------------------------------------------------------------
__global__ void abssum2_kernel(const float* __restrict__ W1, const float* __restrict__ W2,
                               float* __restrict__ part) {
    __shared__ float sred[8];
    const float* W = (blockIdx.x < 256) ? W1 : W2;
    int n = (blockIdx.x < 256) ? NWIN : NWOUT;
    int blk = blockIdx.x & 255;
    float s = 0.f;
    for (int i = blk * blockDim.x + threadIdx.x; i < n; i += 256 * blockDim.x)
        s += fabsf(W[i]);
    float tot = block_reduce_sum(s, sred);
    if (threadIdx.x == 0) part[blockIdx.x] = tot;
}

// Quantize both weights; each block re-reduces partials for the scales.
__global__ void quant2_kernel(const float* __restrict__ W1, const float* __restrict__ W2,
                              __half* __restrict__ B1, __half* __restrict__ B2,
                              const float* __restrict__ part, float* __restrict__ scale) {
    __shared__ float sred[8];
    float t0 = block_reduce_sum(part[threadIdx.x], sred);
    float t1 = block_reduce_sum(part[256 + threadIdx.x], sred);
    float s0 = fmaxf(t0 / (float)NWIN,  1e-5f);
    float s1 = fmaxf(t1 / (float)NWOUT, 1e-5f);
    if (blockIdx.x == 0 && threadIdx.x == 0) { scale[0] = s0; scale[1] = s1; }

    const int total = NWIN + NWOUT;
    for (int i = blockIdx.x * blockDim.x + threadIdx.x; i < total; i += gridDim.x * blockDim.x) {
        if (i < NWIN) {
            float wn = fminf(fmaxf(W1[i] / s0, -1.f), 1.f);
            B1[i] = __float2half_rn(rintf(wn));
        } else {
            int j = i - NWIN;
            float wn = fminf(fmaxf(W2[j] / s1, -1.f), 1.f);
            B2[j] = __float2half_rn(rintf(wn));
        }
    }
}

// ----------------------------------------------------------------------------
// Fused double RMSNorm (x -> rmsnorm(w1) -> rmsnorm(w2)) with fp16 out
// ----------------------------------------------------------------------------
__global__ void rmsnorm2_f16_kernel(const float* __restrict__ in,
                                    const float* __restrict__ w1,
                                    const float* __restrict__ w2,
                                    __half* __restrict__ out) {
    __shared__ float sred[8];
    const int D = 768;
    size_t base = (size_t)blockIdx.x * D;
    float v[3], t[3];
    float ss = 0.f;
    #pragma unroll
    for (int i = 0; i < 3; i++) {
        float x = in[base + threadIdx.x + (i << 8)];
        v[i] = x;
        ss = fmaf(x, x, ss);
    }
    float tot = block_reduce_sum(ss, sred);
    float r1 = rsqrtf(tot / (float)D + 1e-6f);
    float ss2 = 0.f;
    #pragma unroll
    for (int i = 0; i < 3; i++) {
        int c = threadIdx.x + (i << 8);
        t[i] = v[i] * r1 * w1[c];
        ss2 = fmaf(t[i], t[i], ss2);
    }
    float tot2 = block_reduce_sum(ss2, sred);
    float r2 = rsqrtf(tot2 / (float)D + 1e-6f);
    #pragma unroll
    for (int i = 0; i < 3; i++) {
        int c = threadIdx.x + (i << 8);
        out[base + c] = __float2half_rn(t[i] * r2 * w2[c]);
    }
}

// RMSNorm fp16->fp16, half2-vectorized (D = 1536, 3 half2 per thread)
__global__ void rmsnorm_h2h_kernel(const __half* __restrict__ in, const float* __restrict__ w,
                                   __half* __restrict__ out) {
    __shared__ float sred[8];
    const int D = 1536;
    size_t base2 = (size_t)blockIdx.x * (D / 2);
    const __half2* in2 = (const __half2*)in + base2;
    __half2* out2 = (__half2*)out + base2;
    const float2* w2 = (const float2*)w;

    float2 v[3];
    float ss = 0.f;
    #pragma unroll
    for (int i = 0; i < 3; i++) {
        __half2 h = in2[threadIdx.x + (i << 8)];
        float2 f = __half22float2(h);
        v[i] = f;
        ss = fmaf(f.x, f.x, fmaf(f.y, f.y, ss));
    }
    float tot = block_reduce_sum(ss, sred);
    float r = rsqrtf(tot / (float)D + 1e-6f);
    #pragma unroll
    for (int i = 0; i < 3; i++) {
        int c = threadIdx.x + (i << 8);
        float2 ww = w2[c];
        out2[c] = __floats2half2_rn(v[i].x * r * ww.x, v[i].y * r * ww.y);
    }
}

// ----------------------------------------------------------------------------
// fp16 tensor-core GEMM: C[M,N] = (A[M,K] * B[N,K]^T) * scale (+Res)
// BM=128, BN=256, BK=128, 8 warps (2x4), 64x64 warp tiles,
// 2-stage ring, distance-1 prefetch issued after the barrier.
// ----------------------------------------------------------------------------
#define LDSK   136                      // 128 + 8 pad (halfs)
#define TILEA256  (128 * LDSK)
#define TILEB256  (256 * LDSK)
#define GSTG   2
#define GSMEM256 (GSTG * (TILEA256 + TILEB256) * 2)   // 208896 bytes

template <bool HALF_OUT>
__global__ __launch_bounds__(256)
void gemm256_kernel(const __half* __restrict__ A,
                    const __half* __restrict__ B,
                    void* __restrict__ Cv, const float* __restrict__ Res,
                    const float* __restrict__ scalep,
                    int M, int N, int K2) {
    extern __shared__ __half smem_[];
    __half* sA = smem_;
    __half* sB = smem_ + GSTG * TILEA256;

    int tid  = threadIdx.x;
    int lane = tid & 31;
    int warp = tid >> 5;
    int wm = warp & 1;
    int wn = warp >> 1;
    int bm = blockIdx.y * 128;
    int bn = blockIdx.x * 256;

    // loader mapping: 16 chunks (of 8 halfs) per 128-half row
    int lrr = tid >> 4;                  // 0..15
    int lcc = (tid & 15) << 3;           // 0..120
    const __half* AgBase = A + (size_t)bm * K2 + lcc;
    const __half* BgBase = B + (size_t)bn * K2 + lcc;

    uint32_t sAbase = cvta_s(sA);
    uint32_t sBbase = cvta_s(sB);

    int aRow = wm * 64 + (lane & 15);
    int aCol = (lane >> 4) << 3;
    uint32_t aFrag = (uint32_t)((aRow * LDSK + aCol) * 2);
    int bRow = wn * 64 + (((lane >> 4) & 1) << 3) + (lane & 7);
    int bCol = ((lane >> 3) & 1) << 3;
    uint32_t bFrag = (uint32_t)((bRow * LDSK + bCol) * 2);

    float acc[4][8][4];
    #pragma unroll
    for (int i = 0; i < 4; i++)
        #pragma unroll
        for (int j = 0; j < 8; j++)
            #pragma unroll
            for (int k = 0; k < 4; k++) acc[i][j][k] = 0.f;

    int KT = K2 >> 7;        // 128-wide k-tiles

    auto load_stage = [&](int s, int kt) {
        uint32_t ao = sAbase + (uint32_t)(s * TILEA256 * 2);
        uint32_t bo = sBbase + (uint32_t)(s * TILEB256 * 2);
        size_t ko = (size_t)kt << 7;
        #pragma unroll
        for (int i = 0; i < 8; i++) {
            int r = lrr + (i << 4);
            cpa16(ao + (uint32_t)((r * LDSK + lcc) * 2), AgBase + (size_t)r * K2 + ko);
        }
        #pragma unroll
        for (int i = 0; i < 16; i++) {
            int r = lrr + (i << 4);
            cpa16(bo + (uint32_t)((r * LDSK + lcc) * 2), BgBase + (size_t)r * K2 + ko);
        }
    };

    // prologue: stage 0
    load_stage(0, 0); cpa_commit();

    for (int kt = 0; kt < KT; kt++) {
        cpa_wait<0>();
        __syncthreads();
        if (kt + 1 < KT) {
            load_stage((kt + 1) & 1, kt + 1);
            cpa_commit();
        }

        int s = kt & 1;
        uint32_t aS = sAbase + (uint32_t)(s * TILEA256 * 2) + aFrag;
        uint32_t bS = sBbase + (uint32_t)(s * TILEB256 * 2) + bFrag;
        #pragma unroll
        for (int ks = 0; ks < 8; ks++) {
            uint32_t kb = (uint32_t)(ks * 16 * 2);
            uint32_t a[4][4];
            #pragma unroll
            for (int mt = 0; mt < 4; mt++)
                ldsm4(a[mt][0], a[mt][1], a[mt][2], a[mt][3],
                      aS + (uint32_t)(mt * 16 * LDSK * 2) + kb);
            uint32_t bf[8][2];
            #pragma unroll
            for (int p = 0; p < 4; p++)
                ldsm4(bf[2 * p][0], bf[2 * p][1], bf[2 * p + 1][0], bf[2 * p + 1][1],
                      bS + (uint32_t)(p * 16 * LDSK * 2) + kb);
            #pragma unroll
            for (int mt = 0; mt < 4; mt++)
                #pragma unroll
                for (int nt = 0; nt < 8; nt++)
                    mma16816(acc[mt][nt], a[mt], bf[nt]);
        }
    }

    float sc = __ldg(scalep);
    int er = bm + wm * 64 + (lane >> 2);
    int ec = bn + wn * 64 + ((lane & 3) << 1);
    #pragma unroll
    for (int mt = 0; mt < 4; mt++) {
        #pragma unroll
        for (int h = 0; h < 2; h++) {
            int row = er + mt * 16 + h * 8;
            #pragma unroll
            for (int nt = 0; nt < 8; nt++) {
                size_t off = (size_t)row * N + ec + nt * 8;
                float ox = acc[mt][nt][2 * h + 0] * sc;
                float oy = acc[mt][nt][2 * h + 1] * sc;
                if (HALF_OUT) {
                    *(__half2*)((__half*)Cv + off) = __floats2half2_rn(ox, oy);
                } else {
                    float2 o;
                    o.x = ox + Res[off];
                    o.y = oy + Res[off + 1];
                    *(float2*)((float*)Cv + off) = o;
                }
            }
        }
    }
}

// ----------------------------------------------------------------------------
// Causal depthwise conv (K=4) + bias + SiLU — 4 tokens per thread (fp16 io)
// ----------------------------------------------------------------------------
__global__ void conv_silu_kernel(const float* __restrict__ cw, const float* __restrict__ cb) {
    int idx = blockIdx.x * blockDim.x + threadIdx.x;
    const int TOT = (BL / 4) * DIN;
    if (idx >= TOT) return;
    int d = idx % DIN;
    int q = idx / DIN;
    int m0 = q << 2;
    int l0 = m0 & (LL - 1);
    float w0 = cw[d * 4], w1 = cw[d * 4 + 1], w2 = cw[d * 4 + 2], w3 = cw[d * 4 + 3];
    float bias = cb[d];
    float xw[7];
    #pragma unroll
    for (int i = 0; i < 7; i++) {
        int l = l0 + i - 3;
        xw[i] = (l >= 0) ? __half2float(g_xz[(size_t)(m0 + i - 3) * (2 * DIN) + d]) : 0.f;
    }
    #pragma unroll
    for (int t = 0; t < 4; t++) {
        float acc = bias;
        acc = fmaf(xw[t],     w0, acc);
        acc = fmaf(xw[t + 1], w1, acc);
        acc = fmaf(xw[t + 2], w2, acc);
        acc = fmaf(xw[t + 3], w3, acc);
        g_xc[(size_t)(m0 + t) * DIN + d] = __float2half_rn(silu_f(acc));
    }
}

// ----------------------------------------------------------------------------
// dbc = xc @ W_x^T  — tiled GEMM (BM=64 tokens, all 33 outputs, BK=64)
// ----------------------------------------------------------------------------
__global__ __launch_bounds__(256)
void dbc_kernel(const float* __restrict__ Wx) {
    __shared__ float sA[64][65];
    __shared__ float sB[33][65];
    int tid = threadIdx.x;
    int m0 = blockIdx.x * 64;
    int row = tid >> 2;
    int og  = tid & 3;
    float acc[9];
    #pragma unroll
    for (int j = 0; j < 9; j++) acc[j] = 0.f;

    for (int k0 = 0; k0 < DIN; k0 += 64) {
        #pragma unroll
        for (int i = tid; i < 64 * 16; i += 256) {
            int r = i >> 4;
            int c4 = (i & 15) << 2;
            uint2 raw = *(const uint2*)(g_xc + (size_t)(m0 + r) * DIN + k0 + c4);
            __half2 h01 = *(__half2*)&raw.x;
            __half2 h23 = *(__half2*)&raw.y;
            float2 f01 = __half22float2(h01);
            float2 f23 = __half22float2(h23);
            sA[r][c4] = f01.x; sA[r][c4 + 1] = f01.y; sA[r][c4 + 2] = f23.x; sA[r][c4 + 3] = f23.y;
        }
        for (int i = tid; i < 33 * 16; i += 256) {
            int r = i >> 4;
            int c4 = (i & 15) << 2;
            float4 v = *(const float4*)(Wx + (size_t)r * DIN + k0 + c4);
            sB[r][c4] = v.x; sB[r][c4 + 1] = v.y; sB[r][c4 + 2] = v.z; sB[r][c4 + 3] = v.w;
        }
        __syncthreads();
        #pragma unroll 8
        for (int kk = 0; kk < 64; kk++) {
            float a = sA[row][kk];
            #pragma unroll
            for (int j = 0; j < 9; j++) {
                int o = og + 4 * j;
                if (o < 33) acc[j] = fmaf(a, sB[o][kk], acc[j]);
            }
        }
        __syncthreads();
    }
    #pragma unroll
    for (int j = 0; j < 9; j++) {
        int o = og + 4 * j;
        if (o < 33) g_dbc[(size_t)(m0 + row) * 33 + o] = acc[j];
    }
}

// ----------------------------------------------------------------------------
// Chunked selective scan (CH=16, CLEN=128). Thread = one d-channel, 16 states.
// ----------------------------------------------------------------------------
#define SC_DPB 128

__global__ __launch_bounds__(SC_DPB)
void scan_phase1(const float* __restrict__ dt_w, const float* __restrict__ dt_b,
                 const float* __restrict__ A_log) {
    __shared__ float sdbc[32 * 33];
    __shared__ __half su[32][SC_DPB];

    int blk = blockIdx.x;
    const int DB = DIN / SC_DPB;          // 12
    int dblk = blk % DB;
    int tmp = blk / DB;
    int c = tmp % CH;
    int b = tmp / CH;
    int d0 = dblk * SC_DPB;
    int d = d0 + threadIdx.x;

    float A[NN], h[NN];
    #pragma unroll
    for (int j = 0; j < NN; j++) {
        A[j] = -expf(A_log[d * NN + j]);
        h[j] = 0.f;
    }
    bool fast = true;
    #pragma unroll
    for (int j = 1; j < NN; j++)
        fast = fast && (fabsf(A[j] - (float)(j + 1) * A[0]) <= 1e-5f * (float)(j + 1));

    float dtw = dt_w[d], dtb = dt_b[d];
    float sumdelta = 0.f;
    size_t mbase = (size_t)b * LL + (size_t)c * CLEN;

    for (int l0 = 0; l0 < CLEN; l0 += 32) {
        for (int i = threadIdx.x; i < 32 * 33; i += SC_DPB)
            sdbc[i] = g_dbc[(mbase + l0) * 33 + i];
        for (int i = threadIdx.x; i < 32 * SC_DPB; i += SC_DPB) {
            int r = i / SC_DPB, cc = i % SC_DPB;
            su[r][cc] = g_xc[(mbase + l0 + r) * DIN + d0 + cc];
        }
        __syncthreads();
        if (fast) {
            #pragma unroll 4
            for (int li = 0; li < 32; li++) {
                const float* row = sdbc + li * 33;
                float delta = softplus_f(fmaf(row[0], dtw, dtb));
                sumdelta += delta;
                float u = __half2float(su[li][threadIdx.x]);
                float du = delta * u;
                float dA[NN];
                epowers16(__expf(delta * A[0]), dA);
                #pragma unroll
                for (int j = 0; j < NN; j++)
                    h[j] = fmaf(dA[j], h[j], du * row[1 + j]);
            }
        } else {
            #pragma unroll 4
            for (int li = 0; li < 32; li++) {
                const float* row = sdbc + li * 33;
                float delta = softplus_f(fmaf(row[0], dtw, dtb));
                sumdelta += delta;
                float u = __half2float(su[li][threadIdx.x]);
                float du = delta * u;
                #pragma unroll
                for (int j = 0; j < NN; j++) {
                    float dA = __expf(delta * A[j]);
                    h[j] = fmaf(dA, h[j], du * row[1 + j]);
                }
            }
        }
        __syncthreads();
    }
    size_t base = (((size_t)(b * CH + c)) * DIN + d) * NN;
    #pragma unroll
    for (int j = 0; j < NN; j += 4) {
        float4 st; st.x = h[j]; st.y = h[j + 1]; st.z = h[j + 2]; st.w = h[j + 3];
        *(float4*)(g_carry + base + j) = st;
    }
    g_sumd[(b * CH + c) * DIN + d] = sumdelta;
}

__global__ void scan_phase2(const float* __restrict__ A_log) {
    int idx = blockIdx.x * blockDim.x + threadIdx.x;
    if (idx >= BB * DIN * NN) return;
    int n = idx % NN;
    int d = (idx / NN) % DIN;
    int b = idx / (NN * DIN);
    float A = -expf(A_log[d * NN + n]);
    float h = 0.f;
    #pragma unroll
    for (int c = 0; c < CH; c++) {
        size_t o = (((size_t)(b * CH + c)) * DIN + d) * NN + n;
        float loc = g_carry[o];
        g_carry[o] = h;
        float P = __expf(A * g_sumd[(b * CH + c) * DIN + d]);
        h = fmaf(P, h, loc);
    }
}

__global__ __launch_bounds__(SC_DPB)
void scan_phase3(const float* __restrict__ dt_w, const float* __restrict__ dt_b,
                 const float* __restrict__ A_log, const float* __restrict__ D_param) {
    __shared__ float sdbc[32 * 33];
    __shared__ __half su[32][SC_DPB];
    __shared__ __half sz[32][SC_DPB];

    int blk = blockIdx.x;
    const int DB = DIN / SC_DPB;
    int dblk = blk % DB;
    int tmp = blk / DB;
    int c = tmp % CH;
    int b = tmp / CH;
    int d0 = dblk * SC_DPB;
    int d = d0 + threadIdx.x;

    float A[NN], h[NN];
    size_t cbase = (((size_t)(b * CH + c)) * DIN + d) * NN;
    #pragma unroll
    for (int j = 0; j < NN; j += 4) {
        float4 h4 = *(const float4*)(g_carry + cbase + j);
        h[j] = h4.x; h[j + 1] = h4.y; h[j + 2] = h4.z; h[j + 3] = h4.w;
    }
    #pragma unroll
    for (int j = 0; j < NN; j++)
        A[j] = -expf(A_log[d * NN + j]);
    bool fast = true;
    #pragma unroll
    for (int j = 1; j < NN; j++)
        fast = fast && (fabsf(A[j] - (float)(j + 1) * A[0]) <= 1e-5f * (float)(j + 1));

    float dtw = dt_w[d], dtb = dt_b[d], Dp = D_param[d];
    size_t mbase = (size_t)b * LL + (size_t)c * CLEN;

    for (int l0 = 0; l0 < CLEN; l0 += 32) {
        for (int i = threadIdx.x; i < 32 * 33; i += SC_DPB)
            sdbc[i] = g_dbc[(mbase + l0) * 33 + i];
        for (int i = threadIdx.x; i < 32 * SC_DPB; i += SC_DPB) {
            int r = i / SC_DPB, cc = i % SC_DPB;
            su[r][cc] = g_xc[(mbase + l0 + r) * DIN + d0 + cc];
            sz[r][cc] = g_xz[(mbase + l0 + r) * (2 * DIN) + DIN + d0 + cc];
        }
        __syncthreads();
        if (fast) {
            #pragma unroll 4
            for (int li = 0; li < 32; li++) {
                const float* row = sdbc + li * 33;
                float delta = softplus_f(fmaf(row[0], dtw, dtb));
                float u = __half2float(su[li][threadIdx.x]);
                float du = delta * u;
                float dA[NN];
                epowers16(__expf(delta * A[0]), dA);
                float y = 0.f;
                #pragma unroll
                for (int j = 0; j < NN; j++) {
                    h[j] = fmaf(dA[j], h[j], du * row[1 + j]);
                    y = fmaf(h[j], row[17 + j], y);
                }
                float yy = fmaf(u, Dp, y);
                float z = __half2float(sz[li][threadIdx.x]);
                g_y[(mbase + l0 + li) * DIN + d] = __float2half_rn(yy * silu_tanh(z));
            }
        } else {
            #pragma unroll 4
            for (int li = 0; li < 32; li++) {
                const float* row = sdbc + li * 33;
                float delta = softplus_f(fmaf(row[0], dtw, dtb));
                float u = __half2float(su[li][threadIdx.x]);
                float du = delta * u;
                float y = 0.f;
                #pragma unroll
                for (int j = 0; j < NN; j++) {
                    float dA = __expf(delta * A[j]);
                    h[j] = fmaf(dA, h[j], du * row[1 + j]);
                    y = fmaf(h[j], row[17 + j], y);
                }
                float yy = fmaf(u, Dp, y);
                float z = __half2float(sz[li][threadIdx.x]);
                g_y[(mbase + l0 + li) * DIN + d] = __float2half_rn(yy * silu_tanh(z));
            }
        }
        __syncthreads();
    }
}

// ----------------------------------------------------------------------------
// Launch
// ----------------------------------------------------------------------------
extern "C" void kernel_launch(void* const* d_in, const int* in_sizes, int n_in,
                              void* d_out, int out_size) {
    const float* x         = (const float*)d_in[0];
    const float* norm_w    = (const float*)d_in[1];
    const float* in_norm_w = (const float*)d_in[2];
    const float* W_in      = (const float*)d_in[3];
    const float* conv_w    = (const float*)d_in[4];
    const float* conv_b    = (const float*)d_in[5];
    const float* W_x       = (const float*)d_in[6];
    const float* dt_w      = (const float*)d_in[7];
    const float* dt_b      = (const float*)d_in[8];
    const float* A_log     = (const float*)d_in[9];
    const float* D_param   = (const float*)d_in[10];
    const float* out_norm_w = (const float*)d_in[11];
    const float* W_out      = (const float*)d_in[12];
    float* out = (float*)d_out;

    float *p_part, *p_scale;
    __half *p_xz, *p_y, *p_A1, *p_A2, *p_B1, *p_B2;
    cudaGetSymbolAddress((void**)&p_xz,    g_xz);
    cudaGetSymbolAddress((void**)&p_y,     g_y);
    cudaGetSymbolAddress((void**)&p_part,  g_part);
    cudaGetSymbolAddress((void**)&p_scale, g_scale);
    cudaGetSymbolAddress((void**)&p_A1,    g_A1);
    cudaGetSymbolAddress((void**)&p_A2,    g_A2);
    cudaGetSymbolAddress((void**)&p_B1,    g_B1);
    cudaGetSymbolAddress((void**)&p_B2,    g_B2);

    cudaFuncSetAttribute(gemm256_kernel<true>,  cudaFuncAttributeMaxDynamicSharedMemorySize, GSMEM256);
    cudaFuncSetAttribute(gemm256_kernel<false>, cudaFuncAttributeMaxDynamicSharedMemorySize, GSMEM256);

    // 1) Weight scales + quantize
    abssum2_kernel<<<512, 256>>>(W_in, W_out, p_part);
    quant2_kernel<<<2048, 256>>>(W_in, W_out, p_B1, p_B2, p_part, p_scale);

    // 2) Fused double RMSNorm x -> fp16 A1
    rmsnorm2_f16_kernel<<<BL, 256>>>(x, norm_w, in_norm_w, p_A1);

    // 3) xz = (A1 @ B1^T) * scale0   [8192 x 3072] -> fp16
    {
        dim3 grid(2 * DIN / 256, BL / 128);
        gemm256_kernel<true><<<grid, 256, GSMEM256>>>(p_A1, p_B1, p_xz, nullptr, p_scale, BL, 2 * DIN, DM);
    }

    // 4) Causal conv + SiLU (4 tokens/thread)
    conv_silu_kernel<<<((BL / 4) * DIN + 255) / 256, 256>>>(conv_w, conv_b);

    // 5) dbc = xc @ W_x^T (tiled)
    dbc_kernel<<<BL / 64, 256>>>(W_x);

    // 6) Chunked selective scan (CH=16, d-mapped threads)
    scan_phase1<<<BB * CH * (DIN / SC_DPB), SC_DPB>>>(dt_w, dt_b, A_log);
    scan_phase2<<<(BB * DIN * NN + 255) / 256, 256>>>(A_log);
    scan_phase3<<<BB * CH * (DIN / SC_DPB), SC_DPB>>>(dt_w, dt_b, A_log, D_param);

    // 7) RMSNorm y -> fp16 A2 (half2-vectorized)
    rmsnorm_h2h_kernel<<<BL, 256>>>(p_y, out_norm_w, p_A2);

    // 8) out = (A2 @ B2^T) * scale1 + residual(x)   [8192 x 768] fp32
    {
        dim3 grid(DM / 256, BL / 128);
        gemm256_kernel<false><<<grid, 256, GSMEM256>>>(p_A2, p_B2, out, x, p_scale + 1, BL, DM, DIN);
    }
}

// round 15
// speedup vs baseline: 1.0023x; 1.0023x over previous
#include <cuda_runtime.h>
#include <cuda_fp16.h>
#include <math.h>
#include <stdint.h>

// Problem dims (fixed for this instance)
#define BB   4
#define LL   2048
#define DM   768
#define DIN  1536
#define NN   16
#define KK   4
#define BL   (BB*LL)          // 8192 tokens
#define CH   16               // scan chunks
#define CLEN (LL/CH)          // 128

#define NWIN  (2*DIN*DM)      // 2359296
#define NWOUT (DM*DIN)        // 1179648

// ----------------------------------------------------------------------------
// Device scratch
// ----------------------------------------------------------------------------
__device__ __half g_xz [BL*2*DIN];               // bitlinear output [x_path | z] (fp16)
__device__ __half g_xc [BL*DIN];                 // conv + silu (fp16)
__device__ float  g_dbc[BL*33];                  // [dt | B(16) | C(16)]
__device__ __half g_y  [BL*DIN];                 // scan output * silu(z) (fp16)
__device__ __half g_A1[BL*DM];                   // fp16 rmsnorm2(x) [M, DM]
__device__ __half g_A2[BL*DIN];                  // fp16 rmsnorm(y)  [M, DIN]
__device__ __half g_B1[NWIN];                    // ternary W_in  fp16 [3072, 768]
__device__ __half g_B2[NWOUT];                   // ternary W_out fp16 [768, 1536]
__device__ float g_carry[BB*CH*DIN*NN];          // chunk carries / h_in (in-place)
__device__ float g_sumd [BB*CH*DIN];             // per-chunk sum of delta
__device__ float g_part[512];                    // reduction partials
__device__ float g_scale[2];                     // scales for W_in / W_out

// ----------------------------------------------------------------------------
// Helpers
// ----------------------------------------------------------------------------
__device__ __forceinline__ float block_reduce_sum(float v, float* sred) {
    #pragma unroll
    for (int s = 16; s; s >>= 1) v += __shfl_xor_sync(0xffffffffu, v, s);
    int w = threadIdx.x >> 5;
    __syncthreads();
    if ((threadIdx.x & 31) == 0) sred[w] = v;
    __syncthreads();
    float t = 0.f;
    int nw = blockDim.x >> 5;
    for (int i = 0; i < nw; i++) t += sred[i];
    return t;
}

__device__ __forceinline__ float silu_f(float x) {
    return x / (1.f + __expf(-x));
}

// silu via tanh.approx (1 MUFU instead of 2)
__device__ __forceinline__ float silu_tanh(float x) {
    float t;
    asm("tanh.approx.f32 %0, %1;" : "=f"(t) : "f"(x * 0.5f));
    return 0.5f * x * (1.f + t);
}

__device__ __forceinline__ float softplus_f(float x) {
    return (x > 20.f) ? x : __logf(1.f + __expf(x));
}

__device__ __forceinline__ uint32_t cvta_s(const void* p) {
    return (uint32_t)__cvta_generic_to_shared(p);
}

__device__ __forceinline__ void cpa16(uint32_t s, const void* g) {
    asm volatile("cp.async.cg.shared.global [%0], [%1], 16;" :: "r"(s), "l"(g));
}
__device__ __forceinline__ void cpa_commit() {
    asm volatile("cp.async.commit_group;");
}
template <int N_>
__device__ __forceinline__ void cpa_wait() {
    asm volatile("cp.async.wait_group %0;" :: "n"(N_));
}

__device__ __forceinline__ void ldsm4(uint32_t& r0, uint32_t& r1, uint32_t& r2, uint32_t& r3,
                                      uint32_t addr) {
    asm volatile("ldmatrix.sync.aligned.m8n8.x4.shared.b16 {%0,%1,%2,%3}, [%4];"
                 : "=r"(r0), "=r"(r1), "=r"(r2), "=r"(r3) : "r"(addr));
}

__device__ __forceinline__ void mma16816(float* d, const uint32_t* a, const uint32_t* b) {
    asm volatile("mma.sync.aligned.m16n8k16.row.col.f32.f16.f16.f32 "
                 "{%0,%1,%2,%3},{%4,%5,%6,%7},{%8,%9},{%0,%1,%2,%3};"
                 : "+f"(d[0]), "+f"(d[1]), "+f"(d[2]), "+f"(d[3])
                 : "r"(a[0]), "r"(a[1]), "r"(a[2]), "r"(a[3]), "r"(b[0]), "r"(b[1]));
}

// dA[j] = E^(j+1), j=0..15, log-depth multiply tree
__device__ __forceinline__ void epowers16(float E, float* dA) {
    dA[0] = E;
    dA[1] = E * E;
    dA[2] = dA[1] * E;
    dA[3] = dA[1] * dA[1];
    dA[4] = dA[3] * E;
    dA[5] = dA[3] * dA[1];
    dA[6] = dA[3] * dA[2];
    dA[7] = dA[3] * dA[3];
    dA[8] = dA[7] * E;
    dA[9] = dA[7] * dA[1];
    dA[10] = dA[7] * dA[2];
    dA[11] = dA[7] * dA[3];
    dA[12] = dA[7] * dA[4];
    dA[13] = dA[7] * dA[5];
    dA[14] = dA[7] * dA[6];
    dA[15] = dA[7] * dA[7];
}

// ----------------------------------------------------------------------------
// Weight quantization (deterministic 2-phase mean|W|)
// ----------------------------------------------------------------------------
__global__ void abssum2_kernel(const float* __restrict__ W1, const float* __restrict__ W2,
                               float* __restrict__ part) {
    __shared__ float sred[8];
    const float* W = (blockIdx.x < 256) ? W1 : W2;
    int n = (blockIdx.x < 256) ? NWIN : NWOUT;
    int blk = blockIdx.x & 255;
    float s = 0.f;
    for (int i = blk * blockDim.x + threadIdx.x; i < n; i += 256 * blockDim.x)
        s += fabsf(W[i]);
    float tot = block_reduce_sum(s, sred);
    if (threadIdx.x == 0) part[blockIdx.x] = tot;
}

// Quantize both weights; each block re-reduces partials for the scales.
__global__ void quant2_kernel(const float* __restrict__ W1, const float* __restrict__ W2,
                              __half* __restrict__ B1, __half* __restrict__ B2,
                              const float* __restrict__ part, float* __restrict__ scale) {
    __shared__ float sred[8];
    float t0 = block_reduce_sum(part[threadIdx.x], sred);
    float t1 = block_reduce_sum(part[256 + threadIdx.x], sred);
    float s0 = fmaxf(t0 / (float)NWIN,  1e-5f);
    float s1 = fmaxf(t1 / (float)NWOUT, 1e-5f);
    if (blockIdx.x == 0 && threadIdx.x == 0) { scale[0] = s0; scale[1] = s1; }

    const int total = NWIN + NWOUT;
    for (int i = blockIdx.x * blockDim.x + threadIdx.x; i < total; i += gridDim.x * blockDim.x) {
        if (i < NWIN) {
            float wn = fminf(fmaxf(W1[i] / s0, -1.f), 1.f);
            B1[i] = __float2half_rn(rintf(wn));
        } else {
            int j = i - NWIN;
            float wn = fminf(fmaxf(W2[j] / s1, -1.f), 1.f);
            B2[j] = __float2half_rn(rintf(wn));
        }
    }
}

// ----------------------------------------------------------------------------
// Fused double RMSNorm (x -> rmsnorm(w1) -> rmsnorm(w2)) with fp16 out
// ----------------------------------------------------------------------------
__global__ void rmsnorm2_f16_kernel(const float* __restrict__ in,
                                    const float* __restrict__ w1,
                                    const float* __restrict__ w2,
                                    __half* __restrict__ out) {
    __shared__ float sred[8];
    const int D = 768;
    size_t base = (size_t)blockIdx.x * D;
    float v[3], t[3];
    float ss = 0.f;
    #pragma unroll
    for (int i = 0; i < 3; i++) {
        float x = in[base + threadIdx.x + (i << 8)];
        v[i] = x;
        ss = fmaf(x, x, ss);
    }
    float tot = block_reduce_sum(ss, sred);
    float r1 = rsqrtf(tot / (float)D + 1e-6f);
    float ss2 = 0.f;
    #pragma unroll
    for (int i = 0; i < 3; i++) {
        int c = threadIdx.x + (i << 8);
        t[i] = v[i] * r1 * w1[c];
        ss2 = fmaf(t[i], t[i], ss2);
    }
    float tot2 = block_reduce_sum(ss2, sred);
    float r2 = rsqrtf(tot2 / (float)D + 1e-6f);
    #pragma unroll
    for (int i = 0; i < 3; i++) {
        int c = threadIdx.x + (i << 8);
        out[base + c] = __float2half_rn(t[i] * r2 * w2[c]);
    }
}

// RMSNorm fp16->fp16, half2-vectorized (D = 1536, 3 half2 per thread)
__global__ void rmsnorm_h2h_kernel(const __half* __restrict__ in, const float* __restrict__ w,
                                   __half* __restrict__ out) {
    __shared__ float sred[8];
    const int D = 1536;
    size_t base2 = (size_t)blockIdx.x * (D / 2);
    const __half2* in2 = (const __half2*)in + base2;
    __half2* out2 = (__half2*)out + base2;
    const float2* w2 = (const float2*)w;

    float2 v[3];
    float ss = 0.f;
    #pragma unroll
    for (int i = 0; i < 3; i++) {
        __half2 h = in2[threadIdx.x + (i << 8)];
        float2 f = __half22float2(h);
        v[i] = f;
        ss = fmaf(f.x, f.x, fmaf(f.y, f.y, ss));
    }
    float tot = block_reduce_sum(ss, sred);
    float r = rsqrtf(tot / (float)D + 1e-6f);
    #pragma unroll
    for (int i = 0; i < 3; i++) {
        int c = threadIdx.x + (i << 8);
        float2 ww = w2[c];
        out2[c] = __floats2half2_rn(v[i].x * r * ww.x, v[i].y * r * ww.y);
    }
}

// ----------------------------------------------------------------------------
// fp16 tensor-core GEMM: C[M,N] = (A[M,K] * B[N,K]^T) * scale (+Res)
// BM=128, BN=256, BK=64, 8 warps (2x4), 64x64 warp tiles,
// 4-stage cp.async ring (distance 3), register double-buffered fragments
// (ldsm for k-step ks+1 issued before the mma burst of ks).
// ----------------------------------------------------------------------------
#define LDSK   72
#define TILEA256  (128 * LDSK)
#define TILEB256  (256 * LDSK)
#define GSTG   4
#define GSMEM256 (GSTG * (TILEA256 + TILEB256) * 2)   // 221184 bytes

template <bool HALF_OUT>
__global__ __launch_bounds__(256)
void gemm256_kernel(const __half* __restrict__ A,
                    const __half* __restrict__ B,
                    void* __restrict__ Cv, const float* __restrict__ Res,
                    const float* __restrict__ scalep,
                    int M, int N, int K2) {
    extern __shared__ __half smem_[];
    __half* sA = smem_;
    __half* sB = smem_ + GSTG * TILEA256;

    int tid  = threadIdx.x;
    int lane = tid & 31;
    int warp = tid >> 5;
    int wm = warp & 1;
    int wn = warp >> 1;
    int bm = blockIdx.y * 128;
    int bn = blockIdx.x * 256;

    int lr = tid >> 3;
    int lc = (tid & 7) << 3;
    const __half* AgBase = A + (size_t)bm * K2 + lc;
    const __half* BgBase = B + (size_t)bn * K2 + lc;

    uint32_t sAbase = cvta_s(sA);
    uint32_t sBbase = cvta_s(sB);

    int aRow = wm * 64 + (lane & 15);
    int aCol = (lane >> 4) << 3;
    uint32_t aFrag = (uint32_t)((aRow * LDSK + aCol) * 2);
    int bRow = wn * 64 + (((lane >> 4) & 1) << 3) + (lane & 7);
    int bCol = ((lane >> 3) & 1) << 3;
    uint32_t bFrag = (uint32_t)((bRow * LDSK + bCol) * 2);

    float acc[4][8][4];
    #pragma unroll
    for (int i = 0; i < 4; i++)
        #pragma unroll
        for (int j = 0; j < 8; j++)
            #pragma unroll
            for (int k = 0; k < 4; k++) acc[i][j][k] = 0.f;

    int KT = K2 >> 6;

    auto load_stage = [&](int s, int kt) {
        uint32_t ao = sAbase + (uint32_t)(s * TILEA256 * 2);
        uint32_t bo = sBbase + (uint32_t)(s * TILEB256 * 2);
        size_t ko = (size_t)kt << 6;
        #pragma unroll
        for (int i = 0; i < 4; i++) {
            int r = lr + (i << 5);
            cpa16(ao + (uint32_t)((r * LDSK + lc) * 2), AgBase + (size_t)r * K2 + ko);
        }
        #pragma unroll
        for (int i = 0; i < 8; i++) {
            int r = lr + (i << 5);
            cpa16(bo + (uint32_t)((r * LDSK + lc) * 2), BgBase + (size_t)r * K2 + ko);
        }
    };

    // frag loader: all 12 ldsm.x4 for one k-step into buffer p
    uint32_t afr[2][4][4];
    uint32_t bfr[2][8][2];
    auto load_frags = [&](uint32_t aS, uint32_t bS, int ks, int p) {
        uint32_t kb = (uint32_t)(ks * 16 * 2);
        #pragma unroll
        for (int mt = 0; mt < 4; mt++)
            ldsm4(afr[p][mt][0], afr[p][mt][1], afr[p][mt][2], afr[p][mt][3],
                  aS + (uint32_t)(mt * 16 * LDSK * 2) + kb);
        #pragma unroll
        for (int q = 0; q < 4; q++)
            ldsm4(bfr[p][2 * q][0], bfr[p][2 * q][1], bfr[p][2 * q + 1][0], bfr[p][2 * q + 1][1],
                  bS + (uint32_t)(q * 16 * LDSK * 2) + kb);
    };

    // prologue: 3 stages in flight
    load_stage(0, 0); cpa_commit();
    if (KT > 1) { load_stage(1, 1); cpa_commit(); }
    if (KT > 2) { load_stage(2, 2); cpa_commit(); }

    for (int kt = 0; kt < KT; kt++) {
        if (kt + 2 < KT)      cpa_wait<2>();
        else if (kt + 1 < KT) cpa_wait<1>();
        else                  cpa_wait<0>();
        __syncthreads();
        if (kt + 3 < KT) {
            load_stage((kt + 3) & 3, kt + 3);
            cpa_commit();
        }

        int s = kt & 3;
        uint32_t aS = sAbase + (uint32_t)(s * TILEA256 * 2) + aFrag;
        uint32_t bS = sBbase + (uint32_t)(s * TILEB256 * 2) + bFrag;

        load_frags(aS, bS, 0, 0);
        #pragma unroll
        for (int ks = 0; ks < 4; ks++) {
            int p = ks & 1;
            if (ks < 3) load_frags(aS, bS, ks + 1, p ^ 1);
            #pragma unroll
            for (int mt = 0; mt < 4; mt++)
                #pragma unroll
                for (int nt = 0; nt < 8; nt++)
                    mma16816(acc[mt][nt], afr[p][mt], bfr[p][nt]);
        }
    }

    float sc = __ldg(scalep);
    int er = bm + wm * 64 + (lane >> 2);
    int ec = bn + wn * 64 + ((lane & 3) << 1);
    #pragma unroll
    for (int mt = 0; mt < 4; mt++) {
        #pragma unroll
        for (int h = 0; h < 2; h++) {
            int row = er + mt * 16 + h * 8;
            #pragma unroll
            for (int nt = 0; nt < 8; nt++) {
                size_t off = (size_t)row * N + ec + nt * 8;
                float ox = acc[mt][nt][2 * h + 0] * sc;
                float oy = acc[mt][nt][2 * h + 1] * sc;
                if (HALF_OUT) {
                    *(__half2*)((__half*)Cv + off) = __floats2half2_rn(ox, oy);
                } else {
                    float2 o;
                    o.x = ox + Res[off];
                    o.y = oy + Res[off + 1];
                    *(float2*)((float*)Cv + off) = o;
                }
            }
        }
    }
}

// ----------------------------------------------------------------------------
// Causal depthwise conv (K=4) + bias + SiLU — 4 tokens per thread (fp16 io)
// ----------------------------------------------------------------------------
__global__ void conv_silu_kernel(const float* __restrict__ cw, const float* __restrict__ cb) {
    int idx = blockIdx.x * blockDim.x + threadIdx.x;
    const int TOT = (BL / 4) * DIN;
    if (idx >= TOT) return;
    int d = idx % DIN;
    int q = idx / DIN;
    int m0 = q << 2;
    int l0 = m0 & (LL - 1);
    float w0 = cw[d * 4], w1 = cw[d * 4 + 1], w2 = cw[d * 4 + 2], w3 = cw[d * 4 + 3];
    float bias = cb[d];
    float xw[7];
    #pragma unroll
    for (int i = 0; i < 7; i++) {
        int l = l0 + i - 3;
        xw[i] = (l >= 0) ? __half2float(g_xz[(size_t)(m0 + i - 3) * (2 * DIN) + d]) : 0.f;
    }
    #pragma unroll
    for (int t = 0; t < 4; t++) {
        float acc = bias;
        acc = fmaf(xw[t],     w0, acc);
        acc = fmaf(xw[t + 1], w1, acc);
        acc = fmaf(xw[t + 2], w2, acc);
        acc = fmaf(xw[t + 3], w3, acc);
        g_xc[(size_t)(m0 + t) * DIN + d] = __float2half_rn(silu_f(acc));
    }
}

// ----------------------------------------------------------------------------
// dbc = xc @ W_x^T  — tiled GEMM (BM=64 tokens, all 33 outputs, BK=64)
// ----------------------------------------------------------------------------
__global__ __launch_bounds__(256)
void dbc_kernel(const float* __restrict__ Wx) {
    __shared__ float sA[64][65];
    __shared__ float sB[33][65];
    int tid = threadIdx.x;
    int m0 = blockIdx.x * 64;
    int row = tid >> 2;
    int og  = tid & 3;
    float acc[9];
    #pragma unroll
    for (int j = 0; j < 9; j++) acc[j] = 0.f;

    for (int k0 = 0; k0 < DIN; k0 += 64) {
        #pragma unroll
        for (int i = tid; i < 64 * 16; i += 256) {
            int r = i >> 4;
            int c4 = (i & 15) << 2;
            uint2 raw = *(const uint2*)(g_xc + (size_t)(m0 + r) * DIN + k0 + c4);
            __half2 h01 = *(__half2*)&raw.x;
            __half2 h23 = *(__half2*)&raw.y;
            float2 f01 = __half22float2(h01);
            float2 f23 = __half22float2(h23);
            sA[r][c4] = f01.x; sA[r][c4 + 1] = f01.y; sA[r][c4 + 2] = f23.x; sA[r][c4 + 3] = f23.y;
        }
        for (int i = tid; i < 33 * 16; i += 256) {
            int r = i >> 4;
            int c4 = (i & 15) << 2;
            float4 v = *(const float4*)(Wx + (size_t)r * DIN + k0 + c4);
            sB[r][c4] = v.x; sB[r][c4 + 1] = v.y; sB[r][c4 + 2] = v.z; sB[r][c4 + 3] = v.w;
        }
        __syncthreads();
        #pragma unroll 8
        for (int kk = 0; kk < 64; kk++) {
            float a = sA[row][kk];
            #pragma unroll
            for (int j = 0; j < 9; j++) {
                int o = og + 4 * j;
                if (o < 33) acc[j] = fmaf(a, sB[o][kk], acc[j]);
            }
        }
        __syncthreads();
    }
    #pragma unroll
    for (int j = 0; j < 9; j++) {
        int o = og + 4 * j;
        if (o < 33) g_dbc[(size_t)(m0 + row) * 33 + o] = acc[j];
    }
}

// ----------------------------------------------------------------------------
// Chunked selective scan (CH=16, CLEN=128). Thread = one d-channel, 16 states.
// ----------------------------------------------------------------------------
#define SC_DPB 128

__global__ __launch_bounds__(SC_DPB)
void scan_phase1(const float* __restrict__ dt_w, const float* __restrict__ dt_b,
                 const float* __restrict__ A_log) {
    __shared__ float sdbc[32 * 33];
    __shared__ __half su[32][SC_DPB];

    int blk = blockIdx.x;
    const int DB = DIN / SC_DPB;          // 12
    int dblk = blk % DB;
    int tmp = blk / DB;
    int c = tmp % CH;
    int b = tmp / CH;
    int d0 = dblk * SC_DPB;
    int d = d0 + threadIdx.x;

    float A[NN], h[NN];
    #pragma unroll
    for (int j = 0; j < NN; j++) {
        A[j] = -expf(A_log[d * NN + j]);
        h[j] = 0.f;
    }
    bool fast = true;
    #pragma unroll
    for (int j = 1; j < NN; j++)
        fast = fast && (fabsf(A[j] - (float)(j + 1) * A[0]) <= 1e-5f * (float)(j + 1));

    float dtw = dt_w[d], dtb = dt_b[d];
    float sumdelta = 0.f;
    size_t mbase = (size_t)b * LL + (size_t)c * CLEN;

    for (int l0 = 0; l0 < CLEN; l0 += 32) {
        for (int i = threadIdx.x; i < 32 * 33; i += SC_DPB)
            sdbc[i] = g_dbc[(mbase + l0) * 33 + i];
        for (int i = threadIdx.x; i < 32 * SC_DPB; i += SC_DPB) {
            int r = i / SC_DPB, cc = i % SC_DPB;
            su[r][cc] = g_xc[(mbase + l0 + r) * DIN + d0 + cc];
        }
        __syncthreads();
        if (fast) {
            #pragma unroll 4
            for (int li = 0; li < 32; li++) {
                const float* row = sdbc + li * 33;
                float delta = softplus_f(fmaf(row[0], dtw, dtb));
                sumdelta += delta;
                float u = __half2float(su[li][threadIdx.x]);
                float du = delta * u;
                float dA[NN];
                epowers16(__expf(delta * A[0]), dA);
                #pragma unroll
                for (int j = 0; j < NN; j++)
                    h[j] = fmaf(dA[j], h[j], du * row[1 + j]);
            }
        } else {
            #pragma unroll 4
            for (int li = 0; li < 32; li++) {
                const float* row = sdbc + li * 33;
                float delta = softplus_f(fmaf(row[0], dtw, dtb));
                sumdelta += delta;
                float u = __half2float(su[li][threadIdx.x]);
                float du = delta * u;
                #pragma unroll
                for (int j = 0; j < NN; j++) {
                    float dA = __expf(delta * A[j]);
                    h[j] = fmaf(dA, h[j], du * row[1 + j]);
                }
            }
        }
        __syncthreads();
    }
    size_t base = (((size_t)(b * CH + c)) * DIN + d) * NN;
    #pragma unroll
    for (int j = 0; j < NN; j += 4) {
        float4 st; st.x = h[j]; st.y = h[j + 1]; st.z = h[j + 2]; st.w = h[j + 3];
        *(float4*)(g_carry + base + j) = st;
    }
    g_sumd[(b * CH + c) * DIN + d] = sumdelta;
}

__global__ void scan_phase2(const float* __restrict__ A_log) {
    int idx = blockIdx.x * blockDim.x + threadIdx.x;
    if (idx >= BB * DIN * NN) return;
    int n = idx % NN;
    int d = (idx / NN) % DIN;
    int b = idx / (NN * DIN);
    float A = -expf(A_log[d * NN + n]);
    float h = 0.f;
    #pragma unroll
    for (int c = 0; c < CH; c++) {
        size_t o = (((size_t)(b * CH + c)) * DIN + d) * NN + n;
        float loc = g_carry[o];
        g_carry[o] = h;
        float P = __expf(A * g_sumd[(b * CH + c) * DIN + d]);
        h = fmaf(P, h, loc);
    }
}

__global__ __launch_bounds__(SC_DPB)
void scan_phase3(const float* __restrict__ dt_w, const float* __restrict__ dt_b,
                 const float* __restrict__ A_log, const float* __restrict__ D_param) {
    __shared__ float sdbc[32 * 33];
    __shared__ __half su[32][SC_DPB];
    __shared__ __half sz[32][SC_DPB];

    int blk = blockIdx.x;
    const int DB = DIN / SC_DPB;
    int dblk = blk % DB;
    int tmp = blk / DB;
    int c = tmp % CH;
    int b = tmp / CH;
    int d0 = dblk * SC_DPB;
    int d = d0 + threadIdx.x;

    float A[NN], h[NN];
    size_t cbase = (((size_t)(b * CH + c)) * DIN + d) * NN;
    #pragma unroll
    for (int j = 0; j < NN; j += 4) {
        float4 h4 = *(const float4*)(g_carry + cbase + j);
        h[j] = h4.x; h[j + 1] = h4.y; h[j + 2] = h4.z; h[j + 3] = h4.w;
    }
    #pragma unroll
    for (int j = 0; j < NN; j++)
        A[j] = -expf(A_log[d * NN + j]);
    bool fast = true;
    #pragma unroll
    for (int j = 1; j < NN; j++)
        fast = fast && (fabsf(A[j] - (float)(j + 1) * A[0]) <= 1e-5f * (float)(j + 1));

    float dtw = dt_w[d], dtb = dt_b[d], Dp = D_param[d];
    size_t mbase = (size_t)b * LL + (size_t)c * CLEN;

    for (int l0 = 0; l0 < CLEN; l0 += 32) {
        for (int i = threadIdx.x; i < 32 * 33; i += SC_DPB)
            sdbc[i] = g_dbc[(mbase + l0) * 33 + i];
        for (int i = threadIdx.x; i < 32 * SC_DPB; i += SC_DPB) {
            int r = i / SC_DPB, cc = i % SC_DPB;
            su[r][cc] = g_xc[(mbase + l0 + r) * DIN + d0 + cc];
            sz[r][cc] = g_xz[(mbase + l0 + r) * (2 * DIN) + DIN + d0 + cc];
        }
        __syncthreads();
        if (fast) {
            #pragma unroll 4
            for (int li = 0; li < 32; li++) {
                const float* row = sdbc + li * 33;
                float delta = softplus_f(fmaf(row[0], dtw, dtb));
                float u = __half2float(su[li][threadIdx.x]);
                float du = delta * u;
                float dA[NN];
                epowers16(__expf(delta * A[0]), dA);
                float y = 0.f;
                #pragma unroll
                for (int j = 0; j < NN; j++) {
                    h[j] = fmaf(dA[j], h[j], du * row[1 + j]);
                    y = fmaf(h[j], row[17 + j], y);
                }
                float yy = fmaf(u, Dp, y);
                float z = __half2float(sz[li][threadIdx.x]);
                g_y[(mbase + l0 + li) * DIN + d] = __float2half_rn(yy * silu_tanh(z));
            }
        } else {
            #pragma unroll 4
            for (int li = 0; li < 32; li++) {
                const float* row = sdbc + li * 33;
                float delta = softplus_f(fmaf(row[0], dtw, dtb));
                float u = __half2float(su[li][threadIdx.x]);
                float du = delta * u;
                float y = 0.f;
                #pragma unroll
                for (int j = 0; j < NN; j++) {
                    float dA = __expf(delta * A[j]);
                    h[j] = fmaf(dA, h[j], du * row[1 + j]);
                    y = fmaf(h[j], row[17 + j], y);
                }
                float yy = fmaf(u, Dp, y);
                float z = __half2float(sz[li][threadIdx.x]);
                g_y[(mbase + l0 + li) * DIN + d] = __float2half_rn(yy * silu_tanh(z));
            }
        }
        __syncthreads();
    }
}

// ----------------------------------------------------------------------------
// Launch
// ----------------------------------------------------------------------------
extern "C" void kernel_launch(void* const* d_in, const int* in_sizes, int n_in,
                              void* d_out, int out_size) {
    const float* x         = (const float*)d_in[0];
    const float* norm_w    = (const float*)d_in[1];
    const float* in_norm_w = (const float*)d_in[2];
    const float* W_in      = (const float*)d_in[3];
    const float* conv_w    = (const float*)d_in[4];
    const float* conv_b    = (const float*)d_in[5];
    const float* W_x       = (const float*)d_in[6];
    const float* dt_w      = (const float*)d_in[7];
    const float* dt_b      = (const float*)d_in[8];
    const float* A_log     = (const float*)d_in[9];
    const float* D_param   = (const float*)d_in[10];
    const float* out_norm_w = (const float*)d_in[11];
    const float* W_out      = (const float*)d_in[12];
    float* out = (float*)d_out;

    float *p_part, *p_scale;
    __half *p_xz, *p_y, *p_A1, *p_A2, *p_B1, *p_B2;
    cudaGetSymbolAddress((void**)&p_xz,    g_xz);
    cudaGetSymbolAddress((void**)&p_y,     g_y);
    cudaGetSymbolAddress((void**)&p_part,  g_part);
    cudaGetSymbolAddress((void**)&p_scale, g_scale);
    cudaGetSymbolAddress((void**)&p_A1,    g_A1);
    cudaGetSymbolAddress((void**)&p_A2,    g_A2);
    cudaGetSymbolAddress((void**)&p_B1,    g_B1);
    cudaGetSymbolAddress((void**)&p_B2,    g_B2);

    cudaFuncSetAttribute(gemm256_kernel<true>,  cudaFuncAttributeMaxDynamicSharedMemorySize, GSMEM256);
    cudaFuncSetAttribute(gemm256_kernel<false>, cudaFuncAttributeMaxDynamicSharedMemorySize, GSMEM256);

    // 1) Weight scales + quantize
    abssum2_kernel<<<512, 256>>>(W_in, W_out, p_part);
    quant2_kernel<<<2048, 256>>>(W_in, W_out, p_B1, p_B2, p_part, p_scale);

    // 2) Fused double RMSNorm x -> fp16 A1
    rmsnorm2_f16_kernel<<<BL, 256>>>(x, norm_w, in_norm_w, p_A1);

    // 3) xz = (A1 @ B1^T) * scale0   [8192 x 3072] -> fp16
    {
        dim3 grid(2 * DIN / 256, BL / 128);
        gemm256_kernel<true><<<grid, 256, GSMEM256>>>(p_A1, p_B1, p_xz, nullptr, p_scale, BL, 2 * DIN, DM);
    }

    // 4) Causal conv + SiLU (4 tokens/thread)
    conv_silu_kernel<<<((BL / 4) * DIN + 255) / 256, 256>>>(conv_w, conv_b);

    // 5) dbc = xc @ W_x^T (tiled)
    dbc_kernel<<<BL / 64, 256>>>(W_x);

    // 6) Chunked selective scan (CH=16, d-mapped threads)
    scan_phase1<<<BB * CH * (DIN / SC_DPB), SC_DPB>>>(dt_w, dt_b, A_log);
    scan_phase2<<<(BB * DIN * NN + 255) / 256, 256>>>(A_log);
    scan_phase3<<<BB * CH * (DIN / SC_DPB), SC_DPB>>>(dt_w, dt_b, A_log, D_param);

    // 7) RMSNorm y -> fp16 A2 (half2-vectorized)
    rmsnorm_h2h_kernel<<<BL, 256>>>(p_y, out_norm_w, p_A2);

    // 8) out = (A2 @ B2^T) * scale1 + residual(x)   [8192 x 768] fp32
    {
        dim3 grid(DM / 256, BL / 128);
        gemm256_kernel<false><<<grid, 256, GSMEM256>>>(p_A2, p_B2, out, x, p_scale + 1, BL, DM, DIN);
    }
}

// round 16
// speedup vs baseline: 1.0149x; 1.0126x over previous
#include <cuda_runtime.h>
#include <cuda_fp16.h>
#include <math.h>
#include <stdint.h>

// Problem dims (fixed for this instance)
#define BB   4
#define LL   2048
#define DM   768
#define DIN  1536
#define NN   16
#define KK   4
#define BL   (BB*LL)          // 8192 tokens
#define CH   16               // scan chunks
#define CLEN (LL/CH)          // 128

#define NWIN  (2*DIN*DM)      // 2359296
#define NWOUT (DM*DIN)        // 1179648

// ----------------------------------------------------------------------------
// Device scratch
// ----------------------------------------------------------------------------
__device__ __half g_xz [BL*2*DIN];               // bitlinear output [x_path | z] (fp16)
__device__ __half g_xc [BL*DIN];                 // conv + silu (fp16)
__device__ float  g_dbc[BL*33];                  // [dt | B(16) | C(16)]
__device__ __half g_y  [BL*DIN];                 // scan output * silu(z) (fp16)
__device__ __half g_A1[BL*DM];                   // fp16 rmsnorm2(x) [M, DM]
__device__ __half g_A2[BL*DIN];                  // fp16 rmsnorm(y)  [M, DIN]
__device__ __half g_B1[NWIN];                    // ternary W_in  fp16 [3072, 768]
__device__ __half g_B2[NWOUT];                   // ternary W_out fp16 [768, 1536]
__device__ float g_carry[BB*CH*DIN*NN];          // chunk carries / h_in (in-place)
__device__ float g_sumd [BB*CH*DIN];             // per-chunk sum of delta
__device__ float g_part[512];                    // reduction partials
__device__ float g_scale[2];                     // scales for W_in / W_out

// ----------------------------------------------------------------------------
// Helpers
// ----------------------------------------------------------------------------
__device__ __forceinline__ float block_reduce_sum(float v, float* sred) {
    #pragma unroll
    for (int s = 16; s; s >>= 1) v += __shfl_xor_sync(0xffffffffu, v, s);
    int w = threadIdx.x >> 5;
    __syncthreads();
    if ((threadIdx.x & 31) == 0) sred[w] = v;
    __syncthreads();
    float t = 0.f;
    int nw = blockDim.x >> 5;
    for (int i = 0; i < nw; i++) t += sred[i];
    return t;
}

__device__ __forceinline__ float silu_f(float x) {
    return x / (1.f + __expf(-x));
}

// silu via tanh.approx (1 MUFU instead of 2)
__device__ __forceinline__ float silu_tanh(float x) {
    float t;
    asm("tanh.approx.f32 %0, %1;" : "=f"(t) : "f"(x * 0.5f));
    return 0.5f * x * (1.f + t);
}

__device__ __forceinline__ float softplus_f(float x) {
    return (x > 20.f) ? x : __logf(1.f + __expf(x));
}

__device__ __forceinline__ uint32_t cvta_s(const void* p) {
    return (uint32_t)__cvta_generic_to_shared(p);
}

__device__ __forceinline__ void cpa16(uint32_t s, const void* g) {
    asm volatile("cp.async.cg.shared.global [%0], [%1], 16;" :: "r"(s), "l"(g));
}
__device__ __forceinline__ void cpa_commit() {
    asm volatile("cp.async.commit_group;");
}
template <int N_>
__device__ __forceinline__ void cpa_wait() {
    asm volatile("cp.async.wait_group %0;" :: "n"(N_));
}

__device__ __forceinline__ void ldsm4(uint32_t& r0, uint32_t& r1, uint32_t& r2, uint32_t& r3,
                                      uint32_t addr) {
    asm volatile("ldmatrix.sync.aligned.m8n8.x4.shared.b16 {%0,%1,%2,%3}, [%4];"
                 : "=r"(r0), "=r"(r1), "=r"(r2), "=r"(r3) : "r"(addr));
}

__device__ __forceinline__ void mma16816(float* d, const uint32_t* a, const uint32_t* b) {
    asm volatile("mma.sync.aligned.m16n8k16.row.col.f32.f16.f16.f32 "
                 "{%0,%1,%2,%3},{%4,%5,%6,%7},{%8,%9},{%0,%1,%2,%3};"
                 : "+f"(d[0]), "+f"(d[1]), "+f"(d[2]), "+f"(d[3])
                 : "r"(a[0]), "r"(a[1]), "r"(a[2]), "r"(a[3]), "r"(b[0]), "r"(b[1]));
}

// dA[j] = E^(j+1), j=0..15, log-depth multiply tree
__device__ __forceinline__ void epowers16(float E, float* dA) {
    dA[0] = E;
    dA[1] = E * E;
    dA[2] = dA[1] * E;
    dA[3] = dA[1] * dA[1];
    dA[4] = dA[3] * E;
    dA[5] = dA[3] * dA[1];
    dA[6] = dA[3] * dA[2];
    dA[7] = dA[3] * dA[3];
    dA[8] = dA[7] * E;
    dA[9] = dA[7] * dA[1];
    dA[10] = dA[7] * dA[2];
    dA[11] = dA[7] * dA[3];
    dA[12] = dA[7] * dA[4];
    dA[13] = dA[7] * dA[5];
    dA[14] = dA[7] * dA[6];
    dA[15] = dA[7] * dA[7];
}

// ----------------------------------------------------------------------------
// Fused: abssum of both weights (blocks 0..511) + double RMSNorm of x
// (blocks 512..512+BL-1). Inputs disjoint; runs concurrently on one grid.
// ----------------------------------------------------------------------------
__global__ __launch_bounds__(256)
void abssum_norm_kernel(const float* __restrict__ W1, const float* __restrict__ W2,
                        float* __restrict__ part,
                        const float* __restrict__ xin,
                        const float* __restrict__ nw1, const float* __restrict__ nw2,
                        __half* __restrict__ nout) {
    __shared__ float sred[8];
    if (blockIdx.x < 512) {
        const float* W = (blockIdx.x < 256) ? W1 : W2;
        int n = (blockIdx.x < 256) ? NWIN : NWOUT;
        int blk = blockIdx.x & 255;
        float s = 0.f;
        for (int i = blk * blockDim.x + threadIdx.x; i < n; i += 256 * blockDim.x)
            s += fabsf(W[i]);
        float tot = block_reduce_sum(s, sred);
        if (threadIdx.x == 0) part[blockIdx.x] = tot;
    } else {
        const int D = 768;
        int row = blockIdx.x - 512;
        size_t base = (size_t)row * D;
        float v[3], t[3];
        float ss = 0.f;
        #pragma unroll
        for (int i = 0; i < 3; i++) {
            float x = xin[base + threadIdx.x + (i << 8)];
            v[i] = x;
            ss = fmaf(x, x, ss);
        }
        float tot = block_reduce_sum(ss, sred);
        float r1 = rsqrtf(tot / (float)D + 1e-6f);
        float ss2 = 0.f;
        #pragma unroll
        for (int i = 0; i < 3; i++) {
            int c = threadIdx.x + (i << 8);
            t[i] = v[i] * r1 * nw1[c];
            ss2 = fmaf(t[i], t[i], ss2);
        }
        float tot2 = block_reduce_sum(ss2, sred);
        float r2 = rsqrtf(tot2 / (float)D + 1e-6f);
        #pragma unroll
        for (int i = 0; i < 3; i++) {
            int c = threadIdx.x + (i << 8);
            nout[base + c] = __float2half_rn(t[i] * r2 * nw2[c]);
        }
    }
}

// Quantize both weights; each block re-reduces partials for the scales.
__global__ void quant2_kernel(const float* __restrict__ W1, const float* __restrict__ W2,
                              __half* __restrict__ B1, __half* __restrict__ B2,
                              const float* __restrict__ part, float* __restrict__ scale) {
    __shared__ float sred[8];
    float t0 = block_reduce_sum(part[threadIdx.x], sred);
    float t1 = block_reduce_sum(part[256 + threadIdx.x], sred);
    float s0 = fmaxf(t0 / (float)NWIN,  1e-5f);
    float s1 = fmaxf(t1 / (float)NWOUT, 1e-5f);
    if (blockIdx.x == 0 && threadIdx.x == 0) { scale[0] = s0; scale[1] = s1; }

    const int total = NWIN + NWOUT;
    for (int i = blockIdx.x * blockDim.x + threadIdx.x; i < total; i += gridDim.x * blockDim.x) {
        if (i < NWIN) {
            float wn = fminf(fmaxf(W1[i] / s0, -1.f), 1.f);
            B1[i] = __float2half_rn(rintf(wn));
        } else {
            int j = i - NWIN;
            float wn = fminf(fmaxf(W2[j] / s1, -1.f), 1.f);
            B2[j] = __float2half_rn(rintf(wn));
        }
    }
}

// RMSNorm fp16->fp16, half2-vectorized (D = 1536, 3 half2 per thread)
__global__ void rmsnorm_h2h_kernel(const __half* __restrict__ in, const float* __restrict__ w,
                                   __half* __restrict__ out) {
    __shared__ float sred[8];
    const int D = 1536;
    size_t base2 = (size_t)blockIdx.x * (D / 2);
    const __half2* in2 = (const __half2*)in + base2;
    __half2* out2 = (__half2*)out + base2;
    const float2* w2 = (const float2*)w;

    float2 v[3];
    float ss = 0.f;
    #pragma unroll
    for (int i = 0; i < 3; i++) {
        __half2 h = in2[threadIdx.x + (i << 8)];
        float2 f = __half22float2(h);
        v[i] = f;
        ss = fmaf(f.x, f.x, fmaf(f.y, f.y, ss));
    }
    float tot = block_reduce_sum(ss, sred);
    float r = rsqrtf(tot / (float)D + 1e-6f);
    #pragma unroll
    for (int i = 0; i < 3; i++) {
        int c = threadIdx.x + (i << 8);
        float2 ww = w2[c];
        out2[c] = __floats2half2_rn(v[i].x * r * ww.x, v[i].y * r * ww.y);
    }
}

// ----------------------------------------------------------------------------
// fp16 tensor-core GEMM: C[M,N] = (A[M,K] * B[N,K]^T) * scale (+Res)
// BM=128, BN=256, BK=64, 8 warps (2x4), 64x64 warp tiles,
// 4-stage cp.async ring (prefetch distance 3).
// ----------------------------------------------------------------------------
#define LDSK   72
#define TILEA256  (128 * LDSK)
#define TILEB256  (256 * LDSK)
#define GSTG   4
#define GSMEM256 (GSTG * (TILEA256 + TILEB256) * 2)   // 221184 bytes

template <bool HALF_OUT>
__global__ __launch_bounds__(256)
void gemm256_kernel(const __half* __restrict__ A,
                    const __half* __restrict__ B,
                    void* __restrict__ Cv, const float* __restrict__ Res,
                    const float* __restrict__ scalep,
                    int M, int N, int K2) {
    extern __shared__ __half smem_[];
    __half* sA = smem_;
    __half* sB = smem_ + GSTG * TILEA256;

    int tid  = threadIdx.x;
    int lane = tid & 31;
    int warp = tid >> 5;
    int wm = warp & 1;
    int wn = warp >> 1;
    int bm = blockIdx.y * 128;
    int bn = blockIdx.x * 256;

    int lr = tid >> 3;
    int lc = (tid & 7) << 3;
    const __half* AgBase = A + (size_t)bm * K2 + lc;
    const __half* BgBase = B + (size_t)bn * K2 + lc;

    uint32_t sAbase = cvta_s(sA);
    uint32_t sBbase = cvta_s(sB);

    int aRow = wm * 64 + (lane & 15);
    int aCol = (lane >> 4) << 3;
    uint32_t aFrag = (uint32_t)((aRow * LDSK + aCol) * 2);
    int bRow = wn * 64 + (((lane >> 4) & 1) << 3) + (lane & 7);
    int bCol = ((lane >> 3) & 1) << 3;
    uint32_t bFrag = (uint32_t)((bRow * LDSK + bCol) * 2);

    float acc[4][8][4];
    #pragma unroll
    for (int i = 0; i < 4; i++)
        #pragma unroll
        for (int j = 0; j < 8; j++)
            #pragma unroll
            for (int k = 0; k < 4; k++) acc[i][j][k] = 0.f;

    int KT = K2 >> 6;

    auto load_stage = [&](int s, int kt) {
        uint32_t ao = sAbase + (uint32_t)(s * TILEA256 * 2);
        uint32_t bo = sBbase + (uint32_t)(s * TILEB256 * 2);
        size_t ko = (size_t)kt << 6;
        #pragma unroll
        for (int i = 0; i < 4; i++) {
            int r = lr + (i << 5);
            cpa16(ao + (uint32_t)((r * LDSK + lc) * 2), AgBase + (size_t)r * K2 + ko);
        }
        #pragma unroll
        for (int i = 0; i < 8; i++) {
            int r = lr + (i << 5);
            cpa16(bo + (uint32_t)((r * LDSK + lc) * 2), BgBase + (size_t)r * K2 + ko);
        }
    };

    // prologue: 3 stages in flight
    load_stage(0, 0); cpa_commit();
    if (KT > 1) { load_stage(1, 1); cpa_commit(); }
    if (KT > 2) { load_stage(2, 2); cpa_commit(); }

    for (int kt = 0; kt < KT; kt++) {
        if (kt + 2 < KT)      cpa_wait<2>();
        else if (kt + 1 < KT) cpa_wait<1>();
        else                  cpa_wait<0>();
        __syncthreads();
        if (kt + 3 < KT) {
            load_stage((kt + 3) & 3, kt + 3);
            cpa_commit();
        }

        int s = kt & 3;
        uint32_t aS = sAbase + (uint32_t)(s * TILEA256 * 2) + aFrag;
        uint32_t bS = sBbase + (uint32_t)(s * TILEB256 * 2) + bFrag;
        #pragma unroll
        for (int ks = 0; ks < 4; ks++) {
            uint32_t kb = (uint32_t)(ks * 16 * 2);
            uint32_t a[4][4];
            #pragma unroll
            for (int mt = 0; mt < 4; mt++)
                ldsm4(a[mt][0], a[mt][1], a[mt][2], a[mt][3],
                      aS + (uint32_t)(mt * 16 * LDSK * 2) + kb);
            uint32_t bf[8][2];
            #pragma unroll
            for (int p = 0; p < 4; p++)
                ldsm4(bf[2 * p][0], bf[2 * p][1], bf[2 * p + 1][0], bf[2 * p + 1][1],
                      bS + (uint32_t)(p * 16 * LDSK * 2) + kb);
            #pragma unroll
            for (int mt = 0; mt < 4; mt++)
                #pragma unroll
                for (int nt = 0; nt < 8; nt++)
                    mma16816(acc[mt][nt], a[mt], bf[nt]);
        }
    }

    float sc = __ldg(scalep);
    int er = bm + wm * 64 + (lane >> 2);
    int ec = bn + wn * 64 + ((lane & 3) << 1);
    #pragma unroll
    for (int mt = 0; mt < 4; mt++) {
        #pragma unroll
        for (int h = 0; h < 2; h++) {
            int row = er + mt * 16 + h * 8;
            #pragma unroll
            for (int nt = 0; nt < 8; nt++) {
                size_t off = (size_t)row * N + ec + nt * 8;
                float ox = acc[mt][nt][2 * h + 0] * sc;
                float oy = acc[mt][nt][2 * h + 1] * sc;
                if (HALF_OUT) {
                    *(__half2*)((__half*)Cv + off) = __floats2half2_rn(ox, oy);
                } else {
                    float2 o;
                    o.x = ox + Res[off];
                    o.y = oy + Res[off + 1];
                    *(float2*)((float*)Cv + off) = o;
                }
            }
        }
    }
}

// ----------------------------------------------------------------------------
// Causal depthwise conv (K=4) + bias + SiLU — 4 tokens per thread (fp16 io)
// ----------------------------------------------------------------------------
__global__ void conv_silu_kernel(const float* __restrict__ cw, const float* __restrict__ cb) {
    int idx = blockIdx.x * blockDim.x + threadIdx.x;
    const int TOT = (BL / 4) * DIN;
    if (idx >= TOT) return;
    int d = idx % DIN;
    int q = idx / DIN;
    int m0 = q << 2;
    int l0 = m0 & (LL - 1);
    float w0 = cw[d * 4], w1 = cw[d * 4 + 1], w2 = cw[d * 4 + 2], w3 = cw[d * 4 + 3];
    float bias = cb[d];
    float xw[7];
    #pragma unroll
    for (int i = 0; i < 7; i++) {
        int l = l0 + i - 3;
        xw[i] = (l >= 0) ? __half2float(g_xz[(size_t)(m0 + i - 3) * (2 * DIN) + d]) : 0.f;
    }
    #pragma unroll
    for (int t = 0; t < 4; t++) {
        float acc = bias;
        acc = fmaf(xw[t],     w0, acc);
        acc = fmaf(xw[t + 1], w1, acc);
        acc = fmaf(xw[t + 2], w2, acc);
        acc = fmaf(xw[t + 3], w3, acc);
        g_xc[(size_t)(m0 + t) * DIN + d] = __float2half_rn(silu_f(acc));
    }
}

// ----------------------------------------------------------------------------
// dbc = xc @ W_x^T  — tiled GEMM (BM=64 tokens, all 33 outputs, BK=64)
// ----------------------------------------------------------------------------
__global__ __launch_bounds__(256)
void dbc_kernel(const float* __restrict__ Wx) {
    __shared__ float sA[64][65];
    __shared__ float sB[33][65];
    int tid = threadIdx.x;
    int m0 = blockIdx.x * 64;
    int row = tid >> 2;
    int og  = tid & 3;
    float acc[9];
    #pragma unroll
    for (int j = 0; j < 9; j++) acc[j] = 0.f;

    for (int k0 = 0; k0 < DIN; k0 += 64) {
        #pragma unroll
        for (int i = tid; i < 64 * 16; i += 256) {
            int r = i >> 4;
            int c4 = (i & 15) << 2;
            uint2 raw = *(const uint2*)(g_xc + (size_t)(m0 + r) * DIN + k0 + c4);
            __half2 h01 = *(__half2*)&raw.x;
            __half2 h23 = *(__half2*)&raw.y;
            float2 f01 = __half22float2(h01);
            float2 f23 = __half22float2(h23);
            sA[r][c4] = f01.x; sA[r][c4 + 1] = f01.y; sA[r][c4 + 2] = f23.x; sA[r][c4 + 3] = f23.y;
        }
        for (int i = tid; i < 33 * 16; i += 256) {
            int r = i >> 4;
            int c4 = (i & 15) << 2;
            float4 v = *(const float4*)(Wx + (size_t)r * DIN + k0 + c4);
            sB[r][c4] = v.x; sB[r][c4 + 1] = v.y; sB[r][c4 + 2] = v.z; sB[r][c4 + 3] = v.w;
        }
        __syncthreads();
        #pragma unroll 8
        for (int kk = 0; kk < 64; kk++) {
            float a = sA[row][kk];
            #pragma unroll
            for (int j = 0; j < 9; j++) {
                int o = og + 4 * j;
                if (o < 33) acc[j] = fmaf(a, sB[o][kk], acc[j]);
            }
        }
        __syncthreads();
    }
    #pragma unroll
    for (int j = 0; j < 9; j++) {
        int o = og + 4 * j;
        if (o < 33) g_dbc[(size_t)(m0 + row) * 33 + o] = acc[j];
    }
}

// ----------------------------------------------------------------------------
// Chunked selective scan (CH=16, CLEN=128). Thread = one d-channel, 16 states.
// ----------------------------------------------------------------------------
#define SC_DPB 128

__global__ __launch_bounds__(SC_DPB)
void scan_phase1(const float* __restrict__ dt_w, const float* __restrict__ dt_b,
                 const float* __restrict__ A_log) {
    __shared__ float sdbc[32 * 33];
    __shared__ __half su[32][SC_DPB];

    int blk = blockIdx.x;
    const int DB = DIN / SC_DPB;          // 12
    int dblk = blk % DB;
    int tmp = blk / DB;
    int c = tmp % CH;
    int b = tmp / CH;
    int d0 = dblk * SC_DPB;
    int d = d0 + threadIdx.x;

    float A[NN], h[NN];
    #pragma unroll
    for (int j = 0; j < NN; j++) {
        A[j] = -expf(A_log[d * NN + j]);
        h[j] = 0.f;
    }
    bool fast = true;
    #pragma unroll
    for (int j = 1; j < NN; j++)
        fast = fast && (fabsf(A[j] - (float)(j + 1) * A[0]) <= 1e-5f * (float)(j + 1));

    float dtw = dt_w[d], dtb = dt_b[d];
    float sumdelta = 0.f;
    size_t mbase = (size_t)b * LL + (size_t)c * CLEN;

    for (int l0 = 0; l0 < CLEN; l0 += 32) {
        for (int i = threadIdx.x; i < 32 * 33; i += SC_DPB)
            sdbc[i] = g_dbc[(mbase + l0) * 33 + i];
        for (int i = threadIdx.x; i < 32 * SC_DPB; i += SC_DPB) {
            int r = i / SC_DPB, cc = i % SC_DPB;
            su[r][cc] = g_xc[(mbase + l0 + r) * DIN + d0 + cc];
        }
        __syncthreads();
        if (fast) {
            #pragma unroll 4
            for (int li = 0; li < 32; li++) {
                const float* row = sdbc + li * 33;
                float delta = softplus_f(fmaf(row[0], dtw, dtb));
                sumdelta += delta;
                float u = __half2float(su[li][threadIdx.x]);
                float du = delta * u;
                float dA[NN];
                epowers16(__expf(delta * A[0]), dA);
                #pragma unroll
                for (int j = 0; j < NN; j++)
                    h[j] = fmaf(dA[j], h[j], du * row[1 + j]);
            }
        } else {
            #pragma unroll 4
            for (int li = 0; li < 32; li++) {
                const float* row = sdbc + li * 33;
                float delta = softplus_f(fmaf(row[0], dtw, dtb));
                sumdelta += delta;
                float u = __half2float(su[li][threadIdx.x]);
                float du = delta * u;
                #pragma unroll
                for (int j = 0; j < NN; j++) {
                    float dA = __expf(delta * A[j]);
                    h[j] = fmaf(dA, h[j], du * row[1 + j]);
                }
            }
        }
        __syncthreads();
    }
    size_t base = (((size_t)(b * CH + c)) * DIN + d) * NN;
    #pragma unroll
    for (int j = 0; j < NN; j += 4) {
        float4 st; st.x = h[j]; st.y = h[j + 1]; st.z = h[j + 2]; st.w = h[j + 3];
        *(float4*)(g_carry + base + j) = st;
    }
    g_sumd[(b * CH + c) * DIN + d] = sumdelta;
}

__global__ void scan_phase2(const float* __restrict__ A_log) {
    int idx = blockIdx.x * blockDim.x + threadIdx.x;
    if (idx >= BB * DIN * NN) return;
    int n = idx % NN;
    int d = (idx / NN) % DIN;
    int b = idx / (NN * DIN);
    float A = -expf(A_log[d * NN + n]);
    float h = 0.f;
    #pragma unroll
    for (int c = 0; c < CH; c++) {
        size_t o = (((size_t)(b * CH + c)) * DIN + d) * NN + n;
        float loc = g_carry[o];
        g_carry[o] = h;
        float P = __expf(A * g_sumd[(b * CH + c) * DIN + d]);
        h = fmaf(P, h, loc);
    }
}

__global__ __launch_bounds__(SC_DPB)
void scan_phase3(const float* __restrict__ dt_w, const float* __restrict__ dt_b,
                 const float* __restrict__ A_log, const float* __restrict__ D_param) {
    __shared__ float sdbc[32 * 33];
    __shared__ __half su[32][SC_DPB];
    __shared__ __half sz[32][SC_DPB];

    int blk = blockIdx.x;
    const int DB = DIN / SC_DPB;
    int dblk = blk % DB;
    int tmp = blk / DB;
    int c = tmp % CH;
    int b = tmp / CH;
    int d0 = dblk * SC_DPB;
    int d = d0 + threadIdx.x;

    float A[NN], h[NN];
    size_t cbase = (((size_t)(b * CH + c)) * DIN + d) * NN;
    #pragma unroll
    for (int j = 0; j < NN; j += 4) {
        float4 h4 = *(const float4*)(g_carry + cbase + j);
        h[j] = h4.x; h[j + 1] = h4.y; h[j + 2] = h4.z; h[j + 3] = h4.w;
    }
    #pragma unroll
    for (int j = 0; j < NN; j++)
        A[j] = -expf(A_log[d * NN + j]);
    bool fast = true;
    #pragma unroll
    for (int j = 1; j < NN; j++)
        fast = fast && (fabsf(A[j] - (float)(j + 1) * A[0]) <= 1e-5f * (float)(j + 1));

    float dtw = dt_w[d], dtb = dt_b[d], Dp = D_param[d];
    size_t mbase = (size_t)b * LL + (size_t)c * CLEN;

    for (int l0 = 0; l0 < CLEN; l0 += 32) {
        for (int i = threadIdx.x; i < 32 * 33; i += SC_DPB)
            sdbc[i] = g_dbc[(mbase + l0) * 33 + i];
        for (int i = threadIdx.x; i < 32 * SC_DPB; i += SC_DPB) {
            int r = i / SC_DPB, cc = i % SC_DPB;
            su[r][cc] = g_xc[(mbase + l0 + r) * DIN + d0 + cc];
            sz[r][cc] = g_xz[(mbase + l0 + r) * (2 * DIN) + DIN + d0 + cc];
        }
        __syncthreads();
        if (fast) {
            #pragma unroll 4
            for (int li = 0; li < 32; li++) {
                const float* row = sdbc + li * 33;
                float delta = softplus_f(fmaf(row[0], dtw, dtb));
                float u = __half2float(su[li][threadIdx.x]);
                float du = delta * u;
                float dA[NN];
                epowers16(__expf(delta * A[0]), dA);
                float y = 0.f;
                #pragma unroll
                for (int j = 0; j < NN; j++) {
                    h[j] = fmaf(dA[j], h[j], du * row[1 + j]);
                    y = fmaf(h[j], row[17 + j], y);
                }
                float yy = fmaf(u, Dp, y);
                float z = __half2float(sz[li][threadIdx.x]);
                g_y[(mbase + l0 + li) * DIN + d] = __float2half_rn(yy * silu_tanh(z));
            }
        } else {
            #pragma unroll 4
            for (int li = 0; li < 32; li++) {
                const float* row = sdbc + li * 33;
                float delta = softplus_f(fmaf(row[0], dtw, dtb));
                float u = __half2float(su[li][threadIdx.x]);
                float du = delta * u;
                float y = 0.f;
                #pragma unroll
                for (int j = 0; j < NN; j++) {
                    float dA = __expf(delta * A[j]);
                    h[j] = fmaf(dA, h[j], du * row[1 + j]);
                    y = fmaf(h[j], row[17 + j], y);
                }
                float yy = fmaf(u, Dp, y);
                float z = __half2float(sz[li][threadIdx.x]);
                g_y[(mbase + l0 + li) * DIN + d] = __float2half_rn(yy * silu_tanh(z));
            }
        }
        __syncthreads();
    }
}

// ----------------------------------------------------------------------------
// Launch
// ----------------------------------------------------------------------------
extern "C" void kernel_launch(void* const* d_in, const int* in_sizes, int n_in,
                              void* d_out, int out_size) {
    const float* x         = (const float*)d_in[0];
    const float* norm_w    = (const float*)d_in[1];
    const float* in_norm_w = (const float*)d_in[2];
    const float* W_in      = (const float*)d_in[3];
    const float* conv_w    = (const float*)d_in[4];
    const float* conv_b    = (const float*)d_in[5];
    const float* W_x       = (const float*)d_in[6];
    const float* dt_w      = (const float*)d_in[7];
    const float* dt_b      = (const float*)d_in[8];
    const float* A_log     = (const float*)d_in[9];
    const float* D_param   = (const float*)d_in[10];
    const float* out_norm_w = (const float*)d_in[11];
    const float* W_out      = (const float*)d_in[12];
    float* out = (float*)d_out;

    float *p_part, *p_scale;
    __half *p_xz, *p_y, *p_A1, *p_A2, *p_B1, *p_B2;
    cudaGetSymbolAddress((void**)&p_xz,    g_xz);
    cudaGetSymbolAddress((void**)&p_y,     g_y);
    cudaGetSymbolAddress((void**)&p_part,  g_part);
    cudaGetSymbolAddress((void**)&p_scale, g_scale);
    cudaGetSymbolAddress((void**)&p_A1,    g_A1);
    cudaGetSymbolAddress((void**)&p_A2,    g_A2);
    cudaGetSymbolAddress((void**)&p_B1,    g_B1);
    cudaGetSymbolAddress((void**)&p_B2,    g_B2);

    cudaFuncSetAttribute(gemm256_kernel<true>,  cudaFuncAttributeMaxDynamicSharedMemorySize, GSMEM256);
    cudaFuncSetAttribute(gemm256_kernel<false>, cudaFuncAttributeMaxDynamicSharedMemorySize, GSMEM256);

    // 1) Fused: weight abs-sums + double RMSNorm of x (independent inputs)
    abssum_norm_kernel<<<512 + BL, 256>>>(W_in, W_out, p_part, x, norm_w, in_norm_w, p_A1);

    // 2) Quantize both weights (re-reduces partials; publishes g_scale)
    quant2_kernel<<<2048, 256>>>(W_in, W_out, p_B1, p_B2, p_part, p_scale);

    // 3) xz = (A1 @ B1^T) * scale0   [8192 x 3072] -> fp16
    {
        dim3 grid(2 * DIN / 256, BL / 128);
        gemm256_kernel<true><<<grid, 256, GSMEM256>>>(p_A1, p_B1, p_xz, nullptr, p_scale, BL, 2 * DIN, DM);
    }

    // 4) Causal conv + SiLU (4 tokens/thread)
    conv_silu_kernel<<<((BL / 4) * DIN + 255) / 256, 256>>>(conv_w, conv_b);

    // 5) dbc = xc @ W_x^T (tiled)
    dbc_kernel<<<BL / 64, 256>>>(W_x);

    // 6) Chunked selective scan (CH=16, d-mapped threads)
    scan_phase1<<<BB * CH * (DIN / SC_DPB), SC_DPB>>>(dt_w, dt_b, A_log);
    scan_phase2<<<(BB * DIN * NN + 255) / 256, 256>>>(A_log);
    scan_phase3<<<BB * CH * (DIN / SC_DPB), SC_DPB>>>(dt_w, dt_b, A_log, D_param);

    // 7) RMSNorm y -> fp16 A2 (half2-vectorized)
    rmsnorm_h2h_kernel<<<BL, 256>>>(p_y, out_norm_w, p_A2);

    // 8) out = (A2 @ B2^T) * scale1 + residual(x)   [8192 x 768] fp32
    {
        dim3 grid(DM / 256, BL / 128);
        gemm256_kernel<false><<<grid, 256, GSMEM256>>>(p_A2, p_B2, out, x, p_scale + 1, BL, DM, DIN);
    }
}

// round 17
// speedup vs baseline: 1.0152x; 1.0002x over previous
#include <cuda_runtime.h>
#include <cuda_fp16.h>
#include <math.h>
#include <stdint.h>

// Problem dims (fixed for this instance)
#define BB   4
#define LL   2048
#define DM   768
#define DIN  1536
#define NN   16
#define KK   4
#define BL   (BB*LL)          // 8192 tokens
#define CH   16               // scan chunks
#define CLEN (LL/CH)          // 128

#define NWIN  (2*DIN*DM)      // 2359296
#define NWOUT (DM*DIN)        // 1179648

// ----------------------------------------------------------------------------
// Device scratch
// ----------------------------------------------------------------------------
__device__ __half g_xz [BL*2*DIN];               // bitlinear output [x_path | z] (fp16)
__device__ __half g_xc [BL*DIN];                 // conv + silu (fp16)
__device__ float  g_dbc[BL*33];                  // [dt | B(16) | C(16)]
__device__ __half g_y  [BL*DIN];                 // scan output * silu(z) (fp16)
__device__ __half g_A1[BL*DM];                   // fp16 rmsnorm2(x) [M, DM]
__device__ __half g_A2[BL*DIN];                  // fp16 rmsnorm(y)  [M, DIN]
__device__ __half g_B1[NWIN];                    // ternary W_in  fp16 [3072, 768]
__device__ __half g_B2[NWOUT];                   // ternary W_out fp16 [768, 1536]
__device__ float g_carry[BB*CH*DIN*NN];          // chunk carries / h_in (in-place)
__device__ float g_sumd [BB*CH*DIN];             // per-chunk sum of delta
__device__ float g_part[512];                    // reduction partials
__device__ float g_scale[2];                     // scales for W_in / W_out

// ----------------------------------------------------------------------------
// Helpers
// ----------------------------------------------------------------------------
__device__ __forceinline__ float block_reduce_sum(float v, float* sred) {
    #pragma unroll
    for (int s = 16; s; s >>= 1) v += __shfl_xor_sync(0xffffffffu, v, s);
    int w = threadIdx.x >> 5;
    __syncthreads();
    if ((threadIdx.x & 31) == 0) sred[w] = v;
    __syncthreads();
    float t = 0.f;
    int nw = blockDim.x >> 5;
    for (int i = 0; i < nw; i++) t += sred[i];
    return t;
}

__device__ __forceinline__ float silu_f(float x) {
    return x / (1.f + __expf(-x));
}

// silu via tanh.approx (1 MUFU instead of 2)
__device__ __forceinline__ float silu_tanh(float x) {
    float t;
    asm("tanh.approx.f32 %0, %1;" : "=f"(t) : "f"(x * 0.5f));
    return 0.5f * x * (1.f + t);
}

__device__ __forceinline__ float softplus_f(float x) {
    return (x > 20.f) ? x : __logf(1.f + __expf(x));
}

__device__ __forceinline__ uint32_t cvta_s(const void* p) {
    return (uint32_t)__cvta_generic_to_shared(p);
}

__device__ __forceinline__ void cpa16(uint32_t s, const void* g) {
    asm volatile("cp.async.cg.shared.global [%0], [%1], 16;" :: "r"(s), "l"(g));
}
__device__ __forceinline__ void cpa_commit() {
    asm volatile("cp.async.commit_group;");
}
template <int N_>
__device__ __forceinline__ void cpa_wait() {
    asm volatile("cp.async.wait_group %0;" :: "n"(N_));
}

__device__ __forceinline__ void ldsm4(uint32_t& r0, uint32_t& r1, uint32_t& r2, uint32_t& r3,
                                      uint32_t addr) {
    asm volatile("ldmatrix.sync.aligned.m8n8.x4.shared.b16 {%0,%1,%2,%3}, [%4];"
                 : "=r"(r0), "=r"(r1), "=r"(r2), "=r"(r3) : "r"(addr));
}

__device__ __forceinline__ void mma16816(float* d, const uint32_t* a, const uint32_t* b) {
    asm volatile("mma.sync.aligned.m16n8k16.row.col.f32.f16.f16.f32 "
                 "{%0,%1,%2,%3},{%4,%5,%6,%7},{%8,%9},{%0,%1,%2,%3};"
                 : "+f"(d[0]), "+f"(d[1]), "+f"(d[2]), "+f"(d[3])
                 : "r"(a[0]), "r"(a[1]), "r"(a[2]), "r"(a[3]), "r"(b[0]), "r"(b[1]));
}

// dA[j] = E^(j+1), j=0..15, log-depth multiply tree
__device__ __forceinline__ void epowers16(float E, float* dA) {
    dA[0] = E;
    dA[1] = E * E;
    dA[2] = dA[1] * E;
    dA[3] = dA[1] * dA[1];
    dA[4] = dA[3] * E;
    dA[5] = dA[3] * dA[1];
    dA[6] = dA[3] * dA[2];
    dA[7] = dA[3] * dA[3];
    dA[8] = dA[7] * E;
    dA[9] = dA[7] * dA[1];
    dA[10] = dA[7] * dA[2];
    dA[11] = dA[7] * dA[3];
    dA[12] = dA[7] * dA[4];
    dA[13] = dA[7] * dA[5];
    dA[14] = dA[7] * dA[6];
    dA[15] = dA[7] * dA[7];
}

// ----------------------------------------------------------------------------
// Fused: abssum of both weights (blocks 0..511) + double RMSNorm of x
// ----------------------------------------------------------------------------
__global__ __launch_bounds__(256)
void abssum_norm_kernel(const float* __restrict__ W1, const float* __restrict__ W2,
                        float* __restrict__ part,
                        const float* __restrict__ xin,
                        const float* __restrict__ nw1, const float* __restrict__ nw2,
                        __half* __restrict__ nout) {
    __shared__ float sred[8];
    if (blockIdx.x < 512) {
        const float* W = (blockIdx.x < 256) ? W1 : W2;
        int n = (blockIdx.x < 256) ? NWIN : NWOUT;
        int blk = blockIdx.x & 255;
        float s = 0.f;
        for (int i = blk * blockDim.x + threadIdx.x; i < n; i += 256 * blockDim.x)
            s += fabsf(W[i]);
        float tot = block_reduce_sum(s, sred);
        if (threadIdx.x == 0) part[blockIdx.x] = tot;
    } else {
        const int D = 768;
        int row = blockIdx.x - 512;
        size_t base = (size_t)row * D;
        float v[3], t[3];
        float ss = 0.f;
        #pragma unroll
        for (int i = 0; i < 3; i++) {
            float x = xin[base + threadIdx.x + (i << 8)];
            v[i] = x;
            ss = fmaf(x, x, ss);
        }
        float tot = block_reduce_sum(ss, sred);
        float r1 = rsqrtf(tot / (float)D + 1e-6f);
        float ss2 = 0.f;
        #pragma unroll
        for (int i = 0; i < 3; i++) {
            int c = threadIdx.x + (i << 8);
            t[i] = v[i] * r1 * nw1[c];
            ss2 = fmaf(t[i], t[i], ss2);
        }
        float tot2 = block_reduce_sum(ss2, sred);
        float r2 = rsqrtf(tot2 / (float)D + 1e-6f);
        #pragma unroll
        for (int i = 0; i < 3; i++) {
            int c = threadIdx.x + (i << 8);
            nout[base + c] = __float2half_rn(t[i] * r2 * nw2[c]);
        }
    }
}

// Quantize both weights; each block re-reduces partials for the scales.
__global__ void quant2_kernel(const float* __restrict__ W1, const float* __restrict__ W2,
                              __half* __restrict__ B1, __half* __restrict__ B2,
                              const float* __restrict__ part, float* __restrict__ scale) {
    __shared__ float sred[8];
    float t0 = block_reduce_sum(part[threadIdx.x], sred);
    float t1 = block_reduce_sum(part[256 + threadIdx.x], sred);
    float s0 = fmaxf(t0 / (float)NWIN,  1e-5f);
    float s1 = fmaxf(t1 / (float)NWOUT, 1e-5f);
    if (blockIdx.x == 0 && threadIdx.x == 0) { scale[0] = s0; scale[1] = s1; }

    const int total = NWIN + NWOUT;
    for (int i = blockIdx.x * blockDim.x + threadIdx.x; i < total; i += gridDim.x * blockDim.x) {
        if (i < NWIN) {
            float wn = fminf(fmaxf(W1[i] / s0, -1.f), 1.f);
            B1[i] = __float2half_rn(rintf(wn));
        } else {
            int j = i - NWIN;
            float wn = fminf(fmaxf(W2[j] / s1, -1.f), 1.f);
            B2[j] = __float2half_rn(rintf(wn));
        }
    }
}

// RMSNorm fp16->fp16, half2-vectorized (D = 1536, 3 half2 per thread)
__global__ void rmsnorm_h2h_kernel(const __half* __restrict__ in, const float* __restrict__ w,
                                   __half* __restrict__ out) {
    __shared__ float sred[8];
    const int D = 1536;
    size_t base2 = (size_t)blockIdx.x * (D / 2);
    const __half2* in2 = (const __half2*)in + base2;
    __half2* out2 = (__half2*)out + base2;
    const float2* w2 = (const float2*)w;

    float2 v[3];
    float ss = 0.f;
    #pragma unroll
    for (int i = 0; i < 3; i++) {
        __half2 h = in2[threadIdx.x + (i << 8)];
        float2 f = __half22float2(h);
        v[i] = f;
        ss = fmaf(f.x, f.x, fmaf(f.y, f.y, ss));
    }
    float tot = block_reduce_sum(ss, sred);
    float r = rsqrtf(tot / (float)D + 1e-6f);
    #pragma unroll
    for (int i = 0; i < 3; i++) {
        int c = threadIdx.x + (i << 8);
        float2 ww = w2[c];
        out2[c] = __floats2half2_rn(v[i].x * r * ww.x, v[i].y * r * ww.y);
    }
}

// ----------------------------------------------------------------------------
// fp16 tensor-core GEMM: C[M,N] = (A[M,K] * B[N,K]^T) * scale (+Res)
// BM=128, BN=256, BK=64, 8 warps (2x4), 64x64 warp tiles,
// 4-stage cp.async ring (prefetch distance 3).
// ----------------------------------------------------------------------------
#define LDSK   72
#define TILEA256  (128 * LDSK)
#define TILEB256  (256 * LDSK)
#define GSTG   4
#define GSMEM256 (GSTG * (TILEA256 + TILEB256) * 2)   // 221184 bytes

template <bool HALF_OUT>
__global__ __launch_bounds__(256)
void gemm256_kernel(const __half* __restrict__ A,
                    const __half* __restrict__ B,
                    void* __restrict__ Cv, const float* __restrict__ Res,
                    const float* __restrict__ scalep,
                    int M, int N, int K2) {
    extern __shared__ __half smem_[];
    __half* sA = smem_;
    __half* sB = smem_ + GSTG * TILEA256;

    int tid  = threadIdx.x;
    int lane = tid & 31;
    int warp = tid >> 5;
    int wm = warp & 1;
    int wn = warp >> 1;
    int bm = blockIdx.y * 128;
    int bn = blockIdx.x * 256;

    int lr = tid >> 3;
    int lc = (tid & 7) << 3;
    const __half* AgBase = A + (size_t)bm * K2 + lc;
    const __half* BgBase = B + (size_t)bn * K2 + lc;

    uint32_t sAbase = cvta_s(sA);
    uint32_t sBbase = cvta_s(sB);

    int aRow = wm * 64 + (lane & 15);
    int aCol = (lane >> 4) << 3;
    uint32_t aFrag = (uint32_t)((aRow * LDSK + aCol) * 2);
    int bRow = wn * 64 + (((lane >> 4) & 1) << 3) + (lane & 7);
    int bCol = ((lane >> 3) & 1) << 3;
    uint32_t bFrag = (uint32_t)((bRow * LDSK + bCol) * 2);

    float acc[4][8][4];
    #pragma unroll
    for (int i = 0; i < 4; i++)
        #pragma unroll
        for (int j = 0; j < 8; j++)
            #pragma unroll
            for (int k = 0; k < 4; k++) acc[i][j][k] = 0.f;

    int KT = K2 >> 6;

    auto load_stage = [&](int s, int kt) {
        uint32_t ao = sAbase + (uint32_t)(s * TILEA256 * 2);
        uint32_t bo = sBbase + (uint32_t)(s * TILEB256 * 2);
        size_t ko = (size_t)kt << 6;
        #pragma unroll
        for (int i = 0; i < 4; i++) {
            int r = lr + (i << 5);
            cpa16(ao + (uint32_t)((r * LDSK + lc) * 2), AgBase + (size_t)r * K2 + ko);
        }
        #pragma unroll
        for (int i = 0; i < 8; i++) {
            int r = lr + (i << 5);
            cpa16(bo + (uint32_t)((r * LDSK + lc) * 2), BgBase + (size_t)r * K2 + ko);
        }
    };

    // prologue: 3 stages in flight
    load_stage(0, 0); cpa_commit();
    if (KT > 1) { load_stage(1, 1); cpa_commit(); }
    if (KT > 2) { load_stage(2, 2); cpa_commit(); }

    for (int kt = 0; kt < KT; kt++) {
        if (kt + 2 < KT)      cpa_wait<2>();
        else if (kt + 1 < KT) cpa_wait<1>();
        else                  cpa_wait<0>();
        __syncthreads();
        if (kt + 3 < KT) {
            load_stage((kt + 3) & 3, kt + 3);
            cpa_commit();
        }

        int s = kt & 3;
        uint32_t aS = sAbase + (uint32_t)(s * TILEA256 * 2) + aFrag;
        uint32_t bS = sBbase + (uint32_t)(s * TILEB256 * 2) + bFrag;
        #pragma unroll
        for (int ks = 0; ks < 4; ks++) {
            uint32_t kb = (uint32_t)(ks * 16 * 2);
            uint32_t a[4][4];
            #pragma unroll
            for (int mt = 0; mt < 4; mt++)
                ldsm4(a[mt][0], a[mt][1], a[mt][2], a[mt][3],
                      aS + (uint32_t)(mt * 16 * LDSK * 2) + kb);
            uint32_t bf[8][2];
            #pragma unroll
            for (int p = 0; p < 4; p++)
                ldsm4(bf[2 * p][0], bf[2 * p][1], bf[2 * p + 1][0], bf[2 * p + 1][1],
                      bS + (uint32_t)(p * 16 * LDSK * 2) + kb);
            #pragma unroll
            for (int mt = 0; mt < 4; mt++)
                #pragma unroll
                for (int nt = 0; nt < 8; nt++)
                    mma16816(acc[mt][nt], a[mt], bf[nt]);
        }
    }

    float sc = __ldg(scalep);
    int er = bm + wm * 64 + (lane >> 2);
    int ec = bn + wn * 64 + ((lane & 3) << 1);
    #pragma unroll
    for (int mt = 0; mt < 4; mt++) {
        #pragma unroll
        for (int h = 0; h < 2; h++) {
            int row = er + mt * 16 + h * 8;
            #pragma unroll
            for (int nt = 0; nt < 8; nt++) {
                size_t off = (size_t)row * N + ec + nt * 8;
                float ox = acc[mt][nt][2 * h + 0] * sc;
                float oy = acc[mt][nt][2 * h + 1] * sc;
                if (HALF_OUT) {
                    *(__half2*)((__half*)Cv + off) = __floats2half2_rn(ox, oy);
                } else {
                    float2 o;
                    o.x = ox + Res[off];
                    o.y = oy + Res[off + 1];
                    *(float2*)((float*)Cv + off) = o;
                }
            }
        }
    }
}

// ----------------------------------------------------------------------------
// Causal depthwise conv (K=4) + bias + SiLU — 2 channels x 4 tokens per thread
// (half2-vectorized loads/stores)
// ----------------------------------------------------------------------------
__global__ void conv_silu_kernel(const float* __restrict__ cw, const float* __restrict__ cb) {
    int idx = blockIdx.x * blockDim.x + threadIdx.x;
    const int D2 = DIN / 2;                  // half2 channels
    const int TOT = (BL / 4) * D2;
    if (idx >= TOT) return;
    int d2 = idx % D2;                       // half2 channel index
    int q  = idx / D2;
    int m0 = q << 2;
    int l0 = m0 & (LL - 1);
    int d = d2 << 1;

    // weights for channels d, d+1 (cw is [DIN][4])
    float4 wa = *(const float4*)(cw + (size_t)d * 4);        // ch d: w0..w3
    float4 wb = *(const float4*)(cw + (size_t)(d + 1) * 4);  // ch d+1
    float2 bias = *(const float2*)(cb + d);

    const __half2* xz2 = (const __half2*)g_xz;
    __half2* xc2 = (__half2*)g_xc;
    const size_t rowstride = DIN;            // in half2 units: 2*DIN/2

    float2 xw[7];
    #pragma unroll
    for (int i = 0; i < 7; i++) {
        int l = l0 + i - 3;
        if (l >= 0) {
            __half2 h = xz2[(size_t)(m0 + i - 3) * rowstride + d2];
            xw[i] = __half22float2(h);
        } else {
            xw[i].x = 0.f; xw[i].y = 0.f;
        }
    }
    #pragma unroll
    for (int t = 0; t < 4; t++) {
        float ax = bias.x, ay = bias.y;
        ax = fmaf(xw[t].x,     wa.x, ax);
        ax = fmaf(xw[t + 1].x, wa.y, ax);
        ax = fmaf(xw[t + 2].x, wa.z, ax);
        ax = fmaf(xw[t + 3].x, wa.w, ax);
        ay = fmaf(xw[t].y,     wb.x, ay);
        ay = fmaf(xw[t + 1].y, wb.y, ay);
        ay = fmaf(xw[t + 2].y, wb.z, ay);
        ay = fmaf(xw[t + 3].y, wb.w, ay);
        xc2[(size_t)(m0 + t) * (DIN / 2) + d2] = __floats2half2_rn(silu_f(ax), silu_f(ay));
    }
}

// ----------------------------------------------------------------------------
// dbc = xc @ W_x^T  — tiled GEMM (BM=64 tokens, all 33 outputs, BK=64)
// ----------------------------------------------------------------------------
__global__ __launch_bounds__(256)
void dbc_kernel(const float* __restrict__ Wx) {
    __shared__ float sA[64][65];
    __shared__ float sB[33][65];
    int tid = threadIdx.x;
    int m0 = blockIdx.x * 64;
    int row = tid >> 2;
    int og  = tid & 3;
    float acc[9];
    #pragma unroll
    for (int j = 0; j < 9; j++) acc[j] = 0.f;

    for (int k0 = 0; k0 < DIN; k0 += 64) {
        #pragma unroll
        for (int i = tid; i < 64 * 16; i += 256) {
            int r = i >> 4;
            int c4 = (i & 15) << 2;
            uint2 raw = *(const uint2*)(g_xc + (size_t)(m0 + r) * DIN + k0 + c4);
            __half2 h01 = *(__half2*)&raw.x;
            __half2 h23 = *(__half2*)&raw.y;
            float2 f01 = __half22float2(h01);
            float2 f23 = __half22float2(h23);
            sA[r][c4] = f01.x; sA[r][c4 + 1] = f01.y; sA[r][c4 + 2] = f23.x; sA[r][c4 + 3] = f23.y;
        }
        for (int i = tid; i < 33 * 16; i += 256) {
            int r = i >> 4;
            int c4 = (i & 15) << 2;
            float4 v = *(const float4*)(Wx + (size_t)r * DIN + k0 + c4);
            sB[r][c4] = v.x; sB[r][c4 + 1] = v.y; sB[r][c4 + 2] = v.z; sB[r][c4 + 3] = v.w;
        }
        __syncthreads();
        #pragma unroll 8
        for (int kk = 0; kk < 64; kk++) {
            float a = sA[row][kk];
            #pragma unroll
            for (int j = 0; j < 9; j++) {
                int o = og + 4 * j;
                if (o < 33) acc[j] = fmaf(a, sB[o][kk], acc[j]);
            }
        }
        __syncthreads();
    }
    #pragma unroll
    for (int j = 0; j < 9; j++) {
        int o = og + 4 * j;
        if (o < 33) g_dbc[(size_t)(m0 + row) * 33 + o] = acc[j];
    }
}

// ----------------------------------------------------------------------------
// Chunked selective scan (CH=16, CLEN=128). Thread = one d-channel, 16 states.
// ----------------------------------------------------------------------------
#define SC_DPB 128

__global__ __launch_bounds__(SC_DPB)
void scan_phase1(const float* __restrict__ dt_w, const float* __restrict__ dt_b,
                 const float* __restrict__ A_log) {
    __shared__ float sdbc[32 * 33];
    __shared__ __half su[32][SC_DPB];

    int blk = blockIdx.x;
    const int DB = DIN / SC_DPB;          // 12
    int dblk = blk % DB;
    int tmp = blk / DB;
    int c = tmp % CH;
    int b = tmp / CH;
    int d0 = dblk * SC_DPB;
    int d = d0 + threadIdx.x;

    float A[NN], h[NN];
    #pragma unroll
    for (int j = 0; j < NN; j++) {
        A[j] = -expf(A_log[d * NN + j]);
        h[j] = 0.f;
    }
    bool fast = true;
    #pragma unroll
    for (int j = 1; j < NN; j++)
        fast = fast && (fabsf(A[j] - (float)(j + 1) * A[0]) <= 1e-5f * (float)(j + 1));

    float dtw = dt_w[d], dtb = dt_b[d];
    float sumdelta = 0.f;
    size_t mbase = (size_t)b * LL + (size_t)c * CLEN;

    for (int l0 = 0; l0 < CLEN; l0 += 32) {
        for (int i = threadIdx.x; i < 32 * 33; i += SC_DPB)
            sdbc[i] = g_dbc[(mbase + l0) * 33 + i];
        for (int i = threadIdx.x; i < 32 * SC_DPB; i += SC_DPB) {
            int r = i / SC_DPB, cc = i % SC_DPB;
            su[r][cc] = g_xc[(mbase + l0 + r) * DIN + d0 + cc];
        }
        __syncthreads();
        if (fast) {
            #pragma unroll 4
            for (int li = 0; li < 32; li++) {
                const float* row = sdbc + li * 33;
                float delta = softplus_f(fmaf(row[0], dtw, dtb));
                sumdelta += delta;
                float u = __half2float(su[li][threadIdx.x]);
                float du = delta * u;
                float dA[NN];
                epowers16(__expf(delta * A[0]), dA);
                #pragma unroll
                for (int j = 0; j < NN; j++)
                    h[j] = fmaf(dA[j], h[j], du * row[1 + j]);
            }
        } else {
            #pragma unroll 4
            for (int li = 0; li < 32; li++) {
                const float* row = sdbc + li * 33;
                float delta = softplus_f(fmaf(row[0], dtw, dtb));
                sumdelta += delta;
                float u = __half2float(su[li][threadIdx.x]);
                float du = delta * u;
                #pragma unroll
                for (int j = 0; j < NN; j++) {
                    float dA = __expf(delta * A[j]);
                    h[j] = fmaf(dA, h[j], du * row[1 + j]);
                }
            }
        }
        __syncthreads();
    }
    size_t base = (((size_t)(b * CH + c)) * DIN + d) * NN;
    #pragma unroll
    for (int j = 0; j < NN; j += 4) {
        float4 st; st.x = h[j]; st.y = h[j + 1]; st.z = h[j + 2]; st.w = h[j + 3];
        *(float4*)(g_carry + base + j) = st;
    }
    g_sumd[(b * CH + c) * DIN + d] = sumdelta;
}

__global__ void scan_phase2(const float* __restrict__ A_log) {
    int idx = blockIdx.x * blockDim.x + threadIdx.x;
    if (idx >= BB * DIN * NN) return;
    int n = idx % NN;
    int d = (idx / NN) % DIN;
    int b = idx / (NN * DIN);
    float A = -expf(A_log[d * NN + n]);
    float h = 0.f;
    #pragma unroll
    for (int c = 0; c < CH; c++) {
        size_t o = (((size_t)(b * CH + c)) * DIN + d) * NN + n;
        float loc = g_carry[o];
        g_carry[o] = h;
        float P = __expf(A * g_sumd[(b * CH + c) * DIN + d]);
        h = fmaf(P, h, loc);
    }
}

__global__ __launch_bounds__(SC_DPB)
void scan_phase3(const float* __restrict__ dt_w, const float* __restrict__ dt_b,
                 const float* __restrict__ A_log, const float* __restrict__ D_param) {
    __shared__ float sdbc[32 * 33];
    __shared__ __half su[32][SC_DPB];
    __shared__ __half sz[32][SC_DPB];

    int blk = blockIdx.x;
    const int DB = DIN / SC_DPB;
    int dblk = blk % DB;
    int tmp = blk / DB;
    int c = tmp % CH;
    int b = tmp / CH;
    int d0 = dblk * SC_DPB;
    int d = d0 + threadIdx.x;

    float A[NN], h[NN];
    size_t cbase = (((size_t)(b * CH + c)) * DIN + d) * NN;
    #pragma unroll
    for (int j = 0; j < NN; j += 4) {
        float4 h4 = *(const float4*)(g_carry + cbase + j);
        h[j] = h4.x; h[j + 1] = h4.y; h[j + 2] = h4.z; h[j + 3] = h4.w;
    }
    #pragma unroll
    for (int j = 0; j < NN; j++)
        A[j] = -expf(A_log[d * NN + j]);
    bool fast = true;
    #pragma unroll
    for (int j = 1; j < NN; j++)
        fast = fast && (fabsf(A[j] - (float)(j + 1) * A[0]) <= 1e-5f * (float)(j + 1));

    float dtw = dt_w[d], dtb = dt_b[d], Dp = D_param[d];
    float dtwv = dtw, dtbv = dtb;
    size_t mbase = (size_t)b * LL + (size_t)c * CLEN;

    for (int l0 = 0; l0 < CLEN; l0 += 32) {
        for (int i = threadIdx.x; i < 32 * 33; i += SC_DPB)
            sdbc[i] = g_dbc[(mbase + l0) * 33 + i];
        for (int i = threadIdx.x; i < 32 * SC_DPB; i += SC_DPB) {
            int r = i / SC_DPB, cc = i % SC_DPB;
            su[r][cc] = g_xc[(mbase + l0 + r) * DIN + d0 + cc];
            sz[r][cc] = g_xz[(mbase + l0 + r) * (2 * DIN) + DIN + d0 + cc];
        }
        __syncthreads();
        if (fast) {
            #pragma unroll 4
            for (int li = 0; li < 32; li++) {
                const float* row = sdbc + li * 33;
                float delta = softplus_f(fmaf(row[0], dtwv, dtbv));
                float u = __half2float(su[li][threadIdx.x]);
                float du = delta * u;
                float dA[NN];
                epowers16(__expf(delta * A[0]), dA);
                float y = 0.f;
                #pragma unroll
                for (int j = 0; j < NN; j++) {
                    h[j] = fmaf(dA[j], h[j], du * row[1 + j]);
                    y = fmaf(h[j], row[17 + j], y);
                }
                float yy = fmaf(u, Dp, y);
                float z = __half2float(sz[li][threadIdx.x]);
                g_y[(mbase + l0 + li) * DIN + d] = __float2half_rn(yy * silu_tanh(z));
            }
        } else {
            #pragma unroll 4
            for (int li = 0; li < 32; li++) {
                const float* row = sdbc + li * 33;
                float delta = softplus_f(fmaf(row[0], dtwv, dtbv));
                float u = __half2float(su[li][threadIdx.x]);
                float du = delta * u;
                float y = 0.f;
                #pragma unroll
                for (int j = 0; j < NN; j++) {
                    float dA = __expf(delta * A[j]);
                    h[j] = fmaf(dA, h[j], du * row[1 + j]);
                    y = fmaf(h[j], row[17 + j], y);
                }
                float yy = fmaf(u, Dp, y);
                float z = __half2float(sz[li][threadIdx.x]);
                g_y[(mbase + l0 + li) * DIN + d] = __float2half_rn(yy * silu_tanh(z));
            }
        }
        __syncthreads();
    }
}

// ----------------------------------------------------------------------------
// Launch
// ----------------------------------------------------------------------------
extern "C" void kernel_launch(void* const* d_in, const int* in_sizes, int n_in,
                              void* d_out, int out_size) {
    const float* x         = (const float*)d_in[0];
    const float* norm_w    = (const float*)d_in[1];
    const float* in_norm_w = (const float*)d_in[2];
    const float* W_in      = (const float*)d_in[3];
    const float* conv_w    = (const float*)d_in[4];
    const float* conv_b    = (const float*)d_in[5];
    const float* W_x       = (const float*)d_in[6];
    const float* dt_w      = (const float*)d_in[7];
    const float* dt_b      = (const float*)d_in[8];
    const float* A_log     = (const float*)d_in[9];
    const float* D_param   = (const float*)d_in[10];
    const float* out_norm_w = (const float*)d_in[11];
    const float* W_out      = (const float*)d_in[12];
    float* out = (float*)d_out;

    float *p_part, *p_scale;
    __half *p_xz, *p_y, *p_A1, *p_A2, *p_B1, *p_B2;
    cudaGetSymbolAddress((void**)&p_xz,    g_xz);
    cudaGetSymbolAddress((void**)&p_y,     g_y);
    cudaGetSymbolAddress((void**)&p_part,  g_part);
    cudaGetSymbolAddress((void**)&p_scale, g_scale);
    cudaGetSymbolAddress((void**)&p_A1,    g_A1);
    cudaGetSymbolAddress((void**)&p_A2,    g_A2);
    cudaGetSymbolAddress((void**)&p_B1,    g_B1);
    cudaGetSymbolAddress((void**)&p_B2,    g_B2);

    cudaFuncSetAttribute(gemm256_kernel<true>,  cudaFuncAttributeMaxDynamicSharedMemorySize, GSMEM256);
    cudaFuncSetAttribute(gemm256_kernel<false>, cudaFuncAttributeMaxDynamicSharedMemorySize, GSMEM256);

    // 1) Fused: weight abs-sums + double RMSNorm of x
    abssum_norm_kernel<<<512 + BL, 256>>>(W_in, W_out, p_part, x, norm_w, in_norm_w, p_A1);

    // 2) Quantize both weights
    quant2_kernel<<<2048, 256>>>(W_in, W_out, p_B1, p_B2, p_part, p_scale);

    // 3) xz = (A1 @ B1^T) * scale0   [8192 x 3072] -> fp16
    {
        dim3 grid(2 * DIN / 256, BL / 128);
        gemm256_kernel<true><<<grid, 256, GSMEM256>>>(p_A1, p_B1, p_xz, nullptr, p_scale, BL, 2 * DIN, DM);
    }

    // 4) Causal conv + SiLU (2 channels x 4 tokens per thread, half2)
    conv_silu_kernel<<<((BL / 4) * (DIN / 2) + 255) / 256, 256>>>(conv_w, conv_b);

    // 5) dbc = xc @ W_x^T (tiled)
    dbc_kernel<<<BL / 64, 256>>>(W_x);

    // 6) Chunked selective scan (CH=16, d-mapped threads)
    scan_phase1<<<BB * CH * (DIN / SC_DPB), SC_DPB>>>(dt_w, dt_b, A_log);
    scan_phase2<<<(BB * DIN * NN + 255) / 256, 256>>>(A_log);
    scan_phase3<<<BB * CH * (DIN / SC_DPB), SC_DPB>>>(dt_w, dt_b, A_log, D_param);

    // 7) RMSNorm y -> fp16 A2 (half2-vectorized)
    rmsnorm_h2h_kernel<<<BL, 256>>>(p_y, out_norm_w, p_A2);

    // 8) out = (A2 @ B2^T) * scale1 + residual(x)   [8192 x 768] fp32
    {
        dim3 grid(DM / 256, BL / 128);
        gemm256_kernel<false><<<grid, 256, GSMEM256>>>(p_A2, p_B2, out, x, p_scale + 1, BL, DM, DIN);
    }
}